// round 1
// baseline (speedup 1.0000x reference)
#include <cuda_runtime.h>
#include <math.h>

#define NB 8
#define SL 8192
#define ED 512
#define NH 8
#define DH 64
#define MT (NB*SL)

// Scratch (device globals — no allocation allowed in kernel_launch)
__device__ float g_q[(size_t)MT * ED];     // feature-mapped Q
__device__ float g_k[(size_t)MT * ED];     // feature-mapped K
__device__ float g_v[(size_t)MT * ED];     // V projection
__device__ float g_attn[(size_t)MT * ED];  // attention output before Wo
__device__ float g_kv[NB * NH * DH * DH];  // KV[n,h,m,d]
__device__ float g_ksum[NB * NH * DH];     // sum_s K[n,s,h,d]

__global__ void zero_small()
{
    int i = blockIdx.x * blockDim.x + threadIdx.x;
    if (i < NB * NH * DH * DH) g_kv[i] = 0.f;
    if (i < NB * NH * DH)      g_ksum[i] = 0.f;
}

// C[m, nc] = sum_k A[m,k] * W[nc,k] + bias[nc], optional feat map (elu+1).
// M = 65536, Nc = K = 512 hardcoded. Block tile 128x128, BK=8, 8x8 per thread.
template <int FEAT>
__global__ __launch_bounds__(256) void gemm512(const float* __restrict__ A,
                                               const float* __restrict__ W,
                                               const float* __restrict__ bias,
                                               float* __restrict__ C)
{
    __shared__ float As[8][128];
    __shared__ float Bs[8][128];

    const int tid = threadIdx.x;
    const int bm  = blockIdx.y * 128;
    const int bn  = blockIdx.x * 128;
    const int tx  = tid & 15;
    const int ty  = tid >> 4;
    const int lr  = tid >> 1;         // 0..127
    const int lc  = (tid & 1) * 4;    // 0 or 4

    const float* Ap = A + (size_t)(bm + lr) * ED + lc;
    const float* Wp = W + (size_t)(bn + lr) * ED + lc;

    float acc[8][8];
#pragma unroll
    for (int i = 0; i < 8; i++)
#pragma unroll
        for (int j = 0; j < 8; j++) acc[i][j] = 0.f;

    for (int kt = 0; kt < ED; kt += 8) {
        float4 av = *(const float4*)(Ap + kt);
        float4 wv = *(const float4*)(Wp + kt);
        __syncthreads();
        As[lc + 0][lr] = av.x; As[lc + 1][lr] = av.y;
        As[lc + 2][lr] = av.z; As[lc + 3][lr] = av.w;
        Bs[lc + 0][lr] = wv.x; Bs[lc + 1][lr] = wv.y;
        Bs[lc + 2][lr] = wv.z; Bs[lc + 3][lr] = wv.w;
        __syncthreads();
#pragma unroll
        for (int k = 0; k < 8; k++) {
            float a[8], b[8];
            *(float4*)(a)     = *(const float4*)&As[k][ty * 4];
            *(float4*)(a + 4) = *(const float4*)&As[k][ty * 4 + 64];
            *(float4*)(b)     = *(const float4*)&Bs[k][tx * 4];
            *(float4*)(b + 4) = *(const float4*)&Bs[k][tx * 4 + 64];
#pragma unroll
            for (int i = 0; i < 8; i++)
#pragma unroll
                for (int j = 0; j < 8; j++)
                    acc[i][j] = fmaf(a[i], b[j], acc[i][j]);
        }
    }

    // Epilogue: bias + optional elu(x)+1, vectorized float4 stores.
#pragma unroll
    for (int i = 0; i < 8; i++) {
        const int row = bm + ((i < 4) ? (ty * 4 + i) : (64 + ty * 4 + i - 4));
#pragma unroll
        for (int half = 0; half < 2; half++) {
            const int cbase = bn + tx * 4 + half * 64;
            float4 o;
            float* oo = (float*)&o;
#pragma unroll
            for (int j = 0; j < 4; j++) {
                float x = acc[i][half * 4 + j] + bias[cbase + j];
                if (FEAT) x = (x > 0.f) ? (x + 1.f) : expf(x);
                oo[j] = x;
            }
            *(float4*)&C[(size_t)row * ED + cbase] = o;
        }
    }
}

// KV[n,h,m,d] = sum_s v[n,s,h,m] * K[n,s,h,d];  Ksum[n,h,d] = sum_s K.
// Split-K over s (8 splits), fp32 atomics into zeroed buffers.
__global__ __launch_bounds__(256) void kv_kernel()
{
    __shared__ float Ksh[32][64];
    __shared__ float Vsh[32][64];

    const int tid = threadIdx.x;
    const int sp  = blockIdx.x;   // split 0..7
    const int h   = blockIdx.y;
    const int n   = blockIdx.z;
    const int tx  = tid & 15;
    const int ty  = tid >> 4;
    const int s0  = sp * (SL / 8);

    float acc[4][4];
#pragma unroll
    for (int i = 0; i < 4; i++)
#pragma unroll
        for (int j = 0; j < 4; j++) acc[i][j] = 0.f;
    float ks = 0.f;

    for (int st = 0; st < SL / 8; st += 32) {
        __syncthreads();
#pragma unroll
        for (int t = tid; t < 512; t += 256) {
            const int r = t >> 4;
            const int c = (t & 15) * 4;
            const size_t g = ((size_t)(n * SL + s0 + st + r)) * ED + h * DH + c;
            *(float4*)&Ksh[r][c] = *(const float4*)&g_k[g];
            *(float4*)&Vsh[r][c] = *(const float4*)&g_v[g];
        }
        __syncthreads();
#pragma unroll 8
        for (int ss = 0; ss < 32; ss++) {
            float4 vm = *(const float4*)&Vsh[ss][ty * 4];
            float4 kd = *(const float4*)&Ksh[ss][tx * 4];
            const float a[4] = {vm.x, vm.y, vm.z, vm.w};
            const float b[4] = {kd.x, kd.y, kd.z, kd.w};
#pragma unroll
            for (int i = 0; i < 4; i++)
#pragma unroll
                for (int j = 0; j < 4; j++)
                    acc[i][j] = fmaf(a[i], b[j], acc[i][j]);
        }
        if (tid < 64) {
#pragma unroll 8
            for (int ss = 0; ss < 32; ss++) ks += Ksh[ss][tid];
        }
    }

    const int base = (n * NH + h) * DH * DH;
#pragma unroll
    for (int i = 0; i < 4; i++)
#pragma unroll
        for (int j = 0; j < 4; j++)
            atomicAdd(&g_kv[base + (ty * 4 + i) * DH + tx * 4 + j], acc[i][j]);
    if (tid < 64)
        atomicAdd(&g_ksum[(n * NH + h) * DH + tid], ks);
}

// V[n,l,h,m] = (sum_d Q[n,l,h,d]*KV[n,h,m,d]) / (sum_d Q[n,l,h,d]*Ksum[n,h,d] + eps)
__global__ __launch_bounds__(256) void attn_kernel()
{
    __shared__ float Qs[64][65];    // pad to avoid stride-64 bank aliasing
    __shared__ float KVs[64][65];
    __shared__ float Ksm[64];

    const int tid = threadIdx.x;
    const int lb  = blockIdx.x * 64;
    const int h   = blockIdx.y;
    const int n   = blockIdx.z;
    const int tx  = tid & 15;
    const int ty  = tid >> 4;

    const int kvbase = (n * NH + h) * DH * DH;
    for (int t = tid; t < 4096; t += 256)
        KVs[t >> 6][t & 63] = g_kv[kvbase + t];
    for (int t = tid; t < 4096; t += 256) {
        const int l = t >> 6, d = t & 63;
        Qs[l][d] = g_q[((size_t)(n * SL + lb + l)) * ED + h * DH + d];
    }
    if (tid < 64) Ksm[tid] = g_ksum[(n * NH + h) * DH + tid];
    __syncthreads();

    float acc[4][4];
#pragma unroll
    for (int i = 0; i < 4; i++)
#pragma unroll
        for (int j = 0; j < 4; j++) acc[i][j] = 0.f;
    float z[4] = {0.f, 0.f, 0.f, 0.f};

#pragma unroll 4
    for (int d = 0; d < 64; d++) {
        float q[4], kv[4];
#pragma unroll
        for (int i = 0; i < 4; i++) q[i] = Qs[ty * 4 + i][d];
#pragma unroll
        for (int j = 0; j < 4; j++) kv[j] = KVs[tx * 4 + j][d];
        const float kd = Ksm[d];
#pragma unroll
        for (int i = 0; i < 4; i++) z[i] = fmaf(q[i], kd, z[i]);
#pragma unroll
        for (int i = 0; i < 4; i++)
#pragma unroll
            for (int j = 0; j < 4; j++)
                acc[i][j] = fmaf(q[i], kv[j], acc[i][j]);
    }

#pragma unroll
    for (int i = 0; i < 4; i++) {
        const float zi = 1.f / (z[i] + 1e-6f);
        const int l = lb + ty * 4 + i;
        const size_t ob = ((size_t)(n * SL + l)) * ED + h * DH + tx * 4;
        float4 o;
        o.x = acc[i][0] * zi; o.y = acc[i][1] * zi;
        o.z = acc[i][2] * zi; o.w = acc[i][3] * zi;
        *(float4*)&g_attn[ob] = o;
    }
}

extern "C" void kernel_launch(void* const* d_in, const int* in_sizes, int n_in,
                              void* d_out, int out_size)
{
    const float* q_in = (const float*)d_in[0];
    const float* k_in = (const float*)d_in[1];
    const float* v_in = (const float*)d_in[2];
    const float* Wq   = (const float*)d_in[3];
    const float* bq   = (const float*)d_in[4];
    const float* Wk   = (const float*)d_in[5];
    const float* bk   = (const float*)d_in[6];
    const float* Wv   = (const float*)d_in[7];
    const float* bv   = (const float*)d_in[8];
    const float* Wo   = (const float*)d_in[9];
    const float* bo   = (const float*)d_in[10];
    float* out = (float*)d_out;

    float *pq, *pk, *pv, *pattn;
    cudaGetSymbolAddress((void**)&pq, g_q);
    cudaGetSymbolAddress((void**)&pk, g_k);
    cudaGetSymbolAddress((void**)&pv, g_v);
    cudaGetSymbolAddress((void**)&pattn, g_attn);

    dim3 blk(256);
    dim3 gg(ED / 128, MT / 128);

    zero_small<<<(NB * NH * DH * DH + 255) / 256, 256>>>();
    gemm512<1><<<gg, blk>>>(q_in, Wq, bq, pq);
    gemm512<1><<<gg, blk>>>(k_in, Wk, bk, pk);
    gemm512<0><<<gg, blk>>>(v_in, Wv, bv, pv);
    kv_kernel<<<dim3(8, NH, NB), blk>>>();
    attn_kernel<<<dim3(SL / 64, NH, NB), blk>>>();
    gemm512<0><<<gg, blk>>>(pattn, Wo, bo, out);
}

// round 3
// speedup vs baseline: 2.2024x; 2.2024x over previous
#include <cuda_runtime.h>
#include <cuda_bf16.h>
#include <math.h>
#include <stdint.h>

#define NB 8
#define SL 8192
#define ED 512
#define NH 8
#define DH 64
#define MT (NB*SL)

// ---------------- scratch (device globals; no allocation allowed) ----------
__device__ float g_q[(size_t)MT * ED];
__device__ float g_k[(size_t)MT * ED];
__device__ float g_v[(size_t)MT * ED];
__device__ float g_kv[NB * NH * DH * DH];
__device__ float g_ksum[NB * NH * DH];
// split bf16 buffers (reused sequentially for query/key/value/attn-out)
__device__ __nv_bfloat16 g_xh[(size_t)MT * ED];
__device__ __nv_bfloat16 g_xl[(size_t)MT * ED];
__device__ __nv_bfloat16 g_wh[ED * ED];
__device__ __nv_bfloat16 g_wl[ED * ED];

// ---------------- helpers ---------------------------------------------------
__device__ __forceinline__ uint32_t smem_u32(const void* p) {
    uint32_t a;
    asm("{ .reg .u64 t; cvta.to.shared.u64 t, %1; cvt.u32.u64 %0, t; }" : "=r"(a) : "l"(p));
    return a;
}
__device__ __forceinline__ uint32_t pack2(__nv_bfloat16 a, __nv_bfloat16 b) {
    __nv_bfloat162 t(a, b);
    return *reinterpret_cast<uint32_t*>(&t);
}
__device__ __forceinline__ void cp16(uint32_t s, const void* g) {
    asm volatile("cp.async.cg.shared.global [%0], [%1], 16;" :: "r"(s), "l"(g));
}
#define CP_COMMIT() asm volatile("cp.async.commit_group;" ::: "memory")
#define CP_WAIT(N)  asm volatile("cp.async.wait_group %0;" :: "n"(N) : "memory")

#define LDSM4(r, addr)                                                         \
    asm volatile("ldmatrix.sync.aligned.m8n8.x4.shared.b16 {%0,%1,%2,%3}, [%4];" \
        : "=r"((r)[0]), "=r"((r)[1]), "=r"((r)[2]), "=r"((r)[3]) : "r"(addr))

#define MMA16816(d, a, b0, b1)                                                 \
    asm volatile("mma.sync.aligned.m16n8k16.row.col.f32.bf16.bf16.f32 "        \
        "{%0,%1,%2,%3}, {%4,%5,%6,%7}, {%8,%9}, {%0,%1,%2,%3};"                \
        : "+f"((d)[0]), "+f"((d)[1]), "+f"((d)[2]), "+f"((d)[3])               \
        : "r"((a)[0]), "r"((a)[1]), "r"((a)[2]), "r"((a)[3]), "r"(b0), "r"(b1))

// ---------------- split fp32 -> bf16 hi/lo ----------------------------------
__global__ __launch_bounds__(256) void split_kernel(const float* __restrict__ src,
                                                    __nv_bfloat16* __restrict__ hi,
                                                    __nv_bfloat16* __restrict__ lo,
                                                    int n4)
{
    int i = blockIdx.x * blockDim.x + threadIdx.x;
    if (i >= n4) return;
    float4 v = ((const float4*)src)[i];
    __nv_bfloat16 h0 = __float2bfloat16(v.x), h1 = __float2bfloat16(v.y);
    __nv_bfloat16 h2 = __float2bfloat16(v.z), h3 = __float2bfloat16(v.w);
    __nv_bfloat16 l0 = __float2bfloat16(v.x - __bfloat162float(h0));
    __nv_bfloat16 l1 = __float2bfloat16(v.y - __bfloat162float(h1));
    __nv_bfloat16 l2 = __float2bfloat16(v.z - __bfloat162float(h2));
    __nv_bfloat16 l3 = __float2bfloat16(v.w - __bfloat162float(h3));
    uint2 hp, lp;
    hp.x = pack2(h0, h1); hp.y = pack2(h2, h3);
    lp.x = pack2(l0, l1); lp.y = pack2(l2, l3);
    ((uint2*)hi)[i] = hp;
    ((uint2*)lo)[i] = lp;
}

// ---------------- mma.sync split-bf16 GEMM ----------------------------------
// C[M=65536, 512] = A[M,512] @ W[512,512]^T + bias, FEAT -> elu+1.
// CTA tile 128x256, 8 warps of 64x64. BK=64, cp.async double-buffered.
#define STAGE_SZ 98304   // Ah 16K + Al 16K + Bh 32K + Bl 32K
#define GSMEM    (2 * STAGE_SZ)

__device__ __forceinline__ void load_chunk(uint32_t sbase,
                                           const __nv_bfloat16* __restrict__ Ah,
                                           const __nv_bfloat16* __restrict__ Al,
                                           const __nv_bfloat16* __restrict__ Bh,
                                           const __nv_bfloat16* __restrict__ Bl,
                                           int bm, int bn, int ch, int tid)
{
    const int kc = ch * 64;
#pragma unroll
    for (int i = 0; i < 4; i++) {
        const int idx = tid + i * 256;            // 0..1023
        const int row = idx >> 3;                 // 0..127
        const int c = idx & 7;
        const uint32_t soff = row * 128 + ((c ^ (row & 7)) << 4);
        const size_t goff = (size_t)(bm + row) * ED + kc + c * 8;
        cp16(sbase + soff, Ah + goff);
        cp16(sbase + 16384 + soff, Al + goff);
    }
#pragma unroll
    for (int i = 0; i < 8; i++) {
        const int idx = tid + i * 256;            // 0..2047
        const int row = idx >> 3;                 // 0..255
        const int c = idx & 7;
        const uint32_t soff = row * 128 + ((c ^ (row & 7)) << 4);
        const size_t goff = (size_t)(bn + row) * ED + kc + c * 8;
        cp16(sbase + 32768 + soff, Bh + goff);
        cp16(sbase + 65536 + soff, Bl + goff);
    }
}

template <int FEAT>
__global__ __launch_bounds__(256, 1) void gemm_mma(const __nv_bfloat16* __restrict__ Ah,
                                                   const __nv_bfloat16* __restrict__ Al,
                                                   const __nv_bfloat16* __restrict__ Bh,
                                                   const __nv_bfloat16* __restrict__ Bl,
                                                   const float* __restrict__ bias,
                                                   float* __restrict__ C)
{
    extern __shared__ char smem_raw[];
    const uint32_t sb = smem_u32(smem_raw);

    const int tid = threadIdx.x;
    const int lane = tid & 31;
    const int wid = tid >> 5;
    const int wm = wid >> 2;          // 0..1   (64-row band)
    const int wn = wid & 3;           // 0..3   (64-col band)
    const int bm = blockIdx.y * 128;
    const int bn = blockIdx.x * 256;

    float acc[4][8][4];
#pragma unroll
    for (int i = 0; i < 4; i++)
#pragma unroll
        for (int j = 0; j < 8; j++)
#pragma unroll
            for (int q = 0; q < 4; q++) acc[i][j][q] = 0.f;

    load_chunk(sb, Ah, Al, Bh, Bl, bm, bn, 0, tid);
    CP_COMMIT();

#pragma unroll 1
    for (int ch = 0; ch < 8; ch++) {
        if (ch < 7) {
            load_chunk(sb + ((ch + 1) & 1) * STAGE_SZ, Ah, Al, Bh, Bl, bm, bn, ch + 1, tid);
            CP_COMMIT();
            CP_WAIT(1);
        } else {
            CP_WAIT(0);
        }
        __syncthreads();

        const uint32_t st = sb + (ch & 1) * STAGE_SZ;
        const uint32_t sA = st, sAl = st + 16384, sB = st + 32768, sBl = st + 65536;

#pragma unroll
        for (int s16 = 0; s16 < 4; s16++) {
            uint32_t ah[4][4], al[4][4];
#pragma unroll
            for (int mf = 0; mf < 4; mf++) {
                const int arow = wm * 64 + mf * 16 + (lane & 15);
                const int achk = s16 * 2 + (lane >> 4);
                const uint32_t aoff = arow * 128 + ((achk ^ (arow & 7)) << 4);
                LDSM4(ah[mf], sA + aoff);
                LDSM4(al[mf], sAl + aoff);
            }
#pragma unroll
            for (int nf = 0; nf < 4; nf++) {
                uint32_t bh[4], bl[4];
                const int brow = wn * 64 + nf * 16 + (lane & 7) + ((lane >> 4) << 3);
                const int bchk = s16 * 2 + ((lane >> 3) & 1);
                const uint32_t boff = brow * 128 + ((bchk ^ (brow & 7)) << 4);
                LDSM4(bh, sB + boff);
                LDSM4(bl, sBl + boff);
#pragma unroll
                for (int mf = 0; mf < 4; mf++) {
                    MMA16816(acc[mf][2 * nf],     ah[mf], bh[0], bh[1]);
                    MMA16816(acc[mf][2 * nf + 1], ah[mf], bh[2], bh[3]);
                }
#pragma unroll
                for (int mf = 0; mf < 4; mf++) {
                    MMA16816(acc[mf][2 * nf],     ah[mf], bl[0], bl[1]);
                    MMA16816(acc[mf][2 * nf + 1], ah[mf], bl[2], bl[3]);
                }
#pragma unroll
                for (int mf = 0; mf < 4; mf++) {
                    MMA16816(acc[mf][2 * nf],     al[mf], bh[0], bh[1]);
                    MMA16816(acc[mf][2 * nf + 1], al[mf], bh[2], bh[3]);
                }
            }
        }
        __syncthreads();
    }

    // Epilogue: bias + optional elu+1, float2 stores.
#pragma unroll
    for (int mf = 0; mf < 4; mf++) {
        const int row0 = bm + wm * 64 + mf * 16 + (lane >> 2);
#pragma unroll
        for (int nf8 = 0; nf8 < 8; nf8++) {
            const int col = bn + wn * 64 + nf8 * 8 + (lane & 3) * 2;
            const float b0 = bias[col], b1 = bias[col + 1];
            float x0 = acc[mf][nf8][0] + b0;
            float x1 = acc[mf][nf8][1] + b1;
            float x2 = acc[mf][nf8][2] + b0;
            float x3 = acc[mf][nf8][3] + b1;
            if (FEAT) {
                x0 = (x0 > 0.f) ? (x0 + 1.f) : expf(x0);
                x1 = (x1 > 0.f) ? (x1 + 1.f) : expf(x1);
                x2 = (x2 > 0.f) ? (x2 + 1.f) : expf(x2);
                x3 = (x3 > 0.f) ? (x3 + 1.f) : expf(x3);
            }
            *(float2*)&C[(size_t)row0 * ED + col]       = make_float2(x0, x1);
            *(float2*)&C[(size_t)(row0 + 8) * ED + col] = make_float2(x2, x3);
        }
    }
}

// ---------------- small kernels ---------------------------------------------
__global__ void zero_small()
{
    int i = blockIdx.x * blockDim.x + threadIdx.x;
    if (i < NB * NH * DH * DH) g_kv[i] = 0.f;
    if (i < NB * NH * DH)      g_ksum[i] = 0.f;
}

__global__ __launch_bounds__(256) void kv_kernel()
{
    __shared__ float Ksh[32][64];
    __shared__ float Vsh[32][64];

    const int tid = threadIdx.x;
    const int sp = blockIdx.x;
    const int h = blockIdx.y;
    const int n = blockIdx.z;
    const int tx = tid & 15;
    const int ty = tid >> 4;
    const int s0 = sp * (SL / 8);

    float acc[4][4];
#pragma unroll
    for (int i = 0; i < 4; i++)
#pragma unroll
        for (int j = 0; j < 4; j++) acc[i][j] = 0.f;
    float ks = 0.f;

    for (int st = 0; st < SL / 8; st += 32) {
        __syncthreads();
#pragma unroll
        for (int t = tid; t < 512; t += 256) {
            const int r = t >> 4;
            const int c = (t & 15) * 4;
            const size_t g = ((size_t)(n * SL + s0 + st + r)) * ED + h * DH + c;
            *(float4*)&Ksh[r][c] = *(const float4*)&g_k[g];
            *(float4*)&Vsh[r][c] = *(const float4*)&g_v[g];
        }
        __syncthreads();
#pragma unroll 8
        for (int ss = 0; ss < 32; ss++) {
            float4 vm = *(const float4*)&Vsh[ss][ty * 4];
            float4 kd = *(const float4*)&Ksh[ss][tx * 4];
            const float a[4] = {vm.x, vm.y, vm.z, vm.w};
            const float b[4] = {kd.x, kd.y, kd.z, kd.w};
#pragma unroll
            for (int i = 0; i < 4; i++)
#pragma unroll
                for (int j = 0; j < 4; j++)
                    acc[i][j] = fmaf(a[i], b[j], acc[i][j]);
        }
        if (tid < 64) {
#pragma unroll 8
            for (int ss = 0; ss < 32; ss++) ks += Ksh[ss][tid];
        }
    }

    const int bse = (n * NH + h) * DH * DH;
#pragma unroll
    for (int i = 0; i < 4; i++)
#pragma unroll
        for (int j = 0; j < 4; j++)
            atomicAdd(&g_kv[bse + (ty * 4 + i) * DH + tx * 4 + j], acc[i][j]);
    if (tid < 64)
        atomicAdd(&g_ksum[(n * NH + h) * DH + tid], ks);
}

// writes split bf16 hi/lo directly (input to final GEMM)
__global__ __launch_bounds__(256) void attn_kernel()
{
    __shared__ float Qs[64][65];
    __shared__ float KVs[64][65];
    __shared__ float Ksm[64];

    const int tid = threadIdx.x;
    const int lb = blockIdx.x * 64;
    const int h = blockIdx.y;
    const int n = blockIdx.z;
    const int tx = tid & 15;
    const int ty = tid >> 4;

    const int kvbase = (n * NH + h) * DH * DH;
    for (int t = tid; t < 4096; t += 256)
        KVs[t >> 6][t & 63] = g_kv[kvbase + t];
    for (int t = tid; t < 4096; t += 256) {
        const int l = t >> 6, d = t & 63;
        Qs[l][d] = g_q[((size_t)(n * SL + lb + l)) * ED + h * DH + d];
    }
    if (tid < 64) Ksm[tid] = g_ksum[(n * NH + h) * DH + tid];
    __syncthreads();

    float acc[4][4];
#pragma unroll
    for (int i = 0; i < 4; i++)
#pragma unroll
        for (int j = 0; j < 4; j++) acc[i][j] = 0.f;
    float z[4] = {0.f, 0.f, 0.f, 0.f};

#pragma unroll 4
    for (int d = 0; d < 64; d++) {
        float q[4], kv[4];
#pragma unroll
        for (int i = 0; i < 4; i++) q[i] = Qs[ty * 4 + i][d];
#pragma unroll
        for (int j = 0; j < 4; j++) kv[j] = KVs[tx * 4 + j][d];
        const float kd = Ksm[d];
#pragma unroll
        for (int i = 0; i < 4; i++) z[i] = fmaf(q[i], kd, z[i]);
#pragma unroll
        for (int i = 0; i < 4; i++)
#pragma unroll
            for (int j = 0; j < 4; j++)
                acc[i][j] = fmaf(q[i], kv[j], acc[i][j]);
    }

#pragma unroll
    for (int i = 0; i < 4; i++) {
        const float zi = 1.f / (z[i] + 1e-6f);
        const int l = lb + ty * 4 + i;
        const size_t ob = ((size_t)(n * SL + l)) * ED + h * DH + tx * 4;
        float o0 = acc[i][0] * zi, o1 = acc[i][1] * zi;
        float o2 = acc[i][2] * zi, o3 = acc[i][3] * zi;
        __nv_bfloat16 h0 = __float2bfloat16(o0), h1 = __float2bfloat16(o1);
        __nv_bfloat16 h2 = __float2bfloat16(o2), h3 = __float2bfloat16(o3);
        __nv_bfloat16 l0 = __float2bfloat16(o0 - __bfloat162float(h0));
        __nv_bfloat16 l1 = __float2bfloat16(o1 - __bfloat162float(h1));
        __nv_bfloat16 l2 = __float2bfloat16(o2 - __bfloat162float(h2));
        __nv_bfloat16 l3 = __float2bfloat16(o3 - __bfloat162float(h3));
        uint2 hp, lp;
        hp.x = pack2(h0, h1); hp.y = pack2(h2, h3);
        lp.x = pack2(l0, l1); lp.y = pack2(l2, l3);
        *(uint2*)&g_xh[ob] = hp;
        *(uint2*)&g_xl[ob] = lp;
    }
}

// ---------------- launch -----------------------------------------------------
extern "C" void kernel_launch(void* const* d_in, const int* in_sizes, int n_in,
                              void* d_out, int out_size)
{
    const float* q_in = (const float*)d_in[0];
    const float* k_in = (const float*)d_in[1];
    const float* v_in = (const float*)d_in[2];
    const float* Wq = (const float*)d_in[3];
    const float* bq = (const float*)d_in[4];
    const float* Wk = (const float*)d_in[5];
    const float* bk = (const float*)d_in[6];
    const float* Wv = (const float*)d_in[7];
    const float* bv = (const float*)d_in[8];
    const float* Wo = (const float*)d_in[9];
    const float* bo = (const float*)d_in[10];
    float* out = (float*)d_out;

    float *pq, *pk, *pv;
    __nv_bfloat16 *xh, *xl, *wh, *wl;
    cudaGetSymbolAddress((void**)&pq, g_q);
    cudaGetSymbolAddress((void**)&pk, g_k);
    cudaGetSymbolAddress((void**)&pv, g_v);
    cudaGetSymbolAddress((void**)&xh, g_xh);
    cudaGetSymbolAddress((void**)&xl, g_xl);
    cudaGetSymbolAddress((void**)&wh, g_wh);
    cudaGetSymbolAddress((void**)&wl, g_wl);

    cudaFuncSetAttribute(gemm_mma<0>, cudaFuncAttributeMaxDynamicSharedMemorySize, GSMEM);
    cudaFuncSetAttribute(gemm_mma<1>, cudaFuncAttributeMaxDynamicSharedMemorySize, GSMEM);

    const int n4x = (int)((size_t)MT * ED / 4);   // 8388608
    const int n4w = ED * ED / 4;                  // 65536
    dim3 blk(256);
    dim3 gsx((n4x + 255) / 256);
    dim3 gsw((n4w + 255) / 256);
    dim3 gg(ED / 256, MT / 128);                  // (2, 512)

    zero_small<<<(NB * NH * DH * DH + 255) / 256, 256>>>();

    split_kernel<<<gsx, blk>>>(q_in, xh, xl, n4x);
    split_kernel<<<gsw, blk>>>(Wq, wh, wl, n4w);
    gemm_mma<1><<<gg, blk, GSMEM>>>(xh, xl, wh, wl, bq, pq);

    split_kernel<<<gsx, blk>>>(k_in, xh, xl, n4x);
    split_kernel<<<gsw, blk>>>(Wk, wh, wl, n4w);
    gemm_mma<1><<<gg, blk, GSMEM>>>(xh, xl, wh, wl, bk, pk);

    split_kernel<<<gsx, blk>>>(v_in, xh, xl, n4x);
    split_kernel<<<gsw, blk>>>(Wv, wh, wl, n4w);
    gemm_mma<0><<<gg, blk, GSMEM>>>(xh, xl, wh, wl, bv, pv);

    kv_kernel<<<dim3(8, NH, NB), blk>>>();
    attn_kernel<<<dim3(SL / 64, NH, NB), blk>>>();   // writes xh/xl

    split_kernel<<<gsw, blk>>>(Wo, wh, wl, n4w);
    gemm_mma<0><<<gg, blk, GSMEM>>>(xh, xl, wh, wl, bo, out);
}

// round 4
// speedup vs baseline: 2.3460x; 1.0652x over previous
#include <cuda_runtime.h>
#include <cuda_fp16.h>
#include <math.h>
#include <stdint.h>

#define NB 8
#define SL 8192
#define ED 512
#define NH 8
#define DH 64
#define MT (NB*SL)

// ---------------- scratch (device globals; no allocation allowed) ----------
__device__ float g_q[(size_t)MT * ED];
__device__ float g_k[(size_t)MT * ED];
__device__ float g_v[(size_t)MT * ED];
__device__ float g_attn[(size_t)MT * ED];
__device__ float g_kv[NB * NH * DH * DH];
__device__ float g_ksum[NB * NH * DH];
__device__ __half g_wh[ED * ED];          // fp16 weight (single)

// ---------------- helpers ---------------------------------------------------
__device__ __forceinline__ uint32_t smem_u32(const void* p) {
    uint32_t a;
    asm("{ .reg .u64 t; cvta.to.shared.u64 t, %1; cvt.u32.u64 %0, t; }" : "=r"(a) : "l"(p));
    return a;
}
__device__ __forceinline__ uint32_t pack2h(__half a, __half b) {
    __half2 t(a, b);
    return *reinterpret_cast<uint32_t*>(&t);
}
__device__ __forceinline__ void cp16(uint32_t s, const void* g) {
    asm volatile("cp.async.cg.shared.global [%0], [%1], 16;" :: "r"(s), "l"(g));
}
#define CP_COMMIT() asm volatile("cp.async.commit_group;" ::: "memory")
#define CP_WAIT(N)  asm volatile("cp.async.wait_group %0;" :: "n"(N) : "memory")

#define LDSM4(r, addr)                                                         \
    asm volatile("ldmatrix.sync.aligned.m8n8.x4.shared.b16 {%0,%1,%2,%3}, [%4];" \
        : "=r"((r)[0]), "=r"((r)[1]), "=r"((r)[2]), "=r"((r)[3]) : "r"(addr))

#define MMA16816(d, a, b0, b1)                                                 \
    asm volatile("mma.sync.aligned.m16n8k16.row.col.f32.f16.f16.f32 "          \
        "{%0,%1,%2,%3}, {%4,%5,%6,%7}, {%8,%9}, {%0,%1,%2,%3};"                \
        : "+f"((d)[0]), "+f"((d)[1]), "+f"((d)[2]), "+f"((d)[3])               \
        : "r"((a)[0]), "r"((a)[1]), "r"((a)[2]), "r"((a)[3]), "r"(b0), "r"(b1))

// ---------------- W fp32 -> fp16 --------------------------------------------
__global__ __launch_bounds__(256) void wconv_kernel(const float* __restrict__ src,
                                                    __half* __restrict__ dst, int n4)
{
    int i = blockIdx.x * blockDim.x + threadIdx.x;
    if (i >= n4) return;
    float4 v = ((const float4*)src)[i];
    uint2 p;
    p.x = pack2h(__float2half_rn(v.x), __float2half_rn(v.y));
    p.y = pack2h(__float2half_rn(v.z), __float2half_rn(v.w));
    ((uint2*)dst)[i] = p;
}

// ---------------- fused-convert fp16 split GEMM ------------------------------
// C[M=65536,512] = A_f32[M,512] @ W_f16[512,512]^T + bias; FEAT -> elu+1.
// CTA tile 128x256, 8 warps of 64x64, BK=64, double-buffered.
// Stage: rawA(f32) 32K | Ah 16K | Al 16K | B 32K  = 96K; 2 stages = 192K.
#define RAW_OFF  0
#define AH_OFF   32768
#define AL_OFF   49152
#define B_OFF    65536
#define STAGE_SZ 98304
#define GSMEM    (2 * STAGE_SZ)

__device__ __forceinline__ void issue_loads(uint32_t st,
                                            const float* __restrict__ A,
                                            const __half* __restrict__ Bh,
                                            int bm, int bn, int ch, int tid)
{
    const int kc = ch * 64;
    // raw A: 128 rows x 256B, linear
#pragma unroll
    for (int i = 0; i < 8; i++) {
        const int idx = tid + i * 256;          // 0..2047
        const int row = idx >> 4;
        const int c = idx & 15;
        cp16(st + RAW_OFF + row * 256 + c * 16,
             A + (size_t)(bm + row) * ED + kc + c * 4);
    }
    CP_COMMIT();
    // B fp16: 256 rows x 128B, SW swizzled
#pragma unroll
    for (int i = 0; i < 8; i++) {
        const int idx = tid + i * 256;          // 0..2047
        const int row = idx >> 3;
        const int c = idx & 7;
        cp16(st + B_OFF + row * 128 + ((c ^ (row & 7)) << 4),
             Bh + (size_t)(bn + row) * ED + kc + c * 8);
    }
    CP_COMMIT();
}

__device__ __forceinline__ void convert_A(char* smem_raw, uint32_t stoff, int tid)
{
    const int row = tid >> 1;
    const int half = tid & 1;
    const float4* raw = (const float4*)(smem_raw + stoff + RAW_OFF);
#pragma unroll
    for (int j = 0; j < 8; j++) {
        float4 v = raw[row * 16 + half * 8 + j];
        __half h0 = __float2half_rn(v.x), h1 = __float2half_rn(v.y);
        __half h2 = __float2half_rn(v.z), h3 = __float2half_rn(v.w);
        __half l0 = __float2half_rn(v.x - __half2float(h0));
        __half l1 = __float2half_rn(v.y - __half2float(h1));
        __half l2 = __float2half_rn(v.z - __half2float(h2));
        __half l3 = __float2half_rn(v.w - __half2float(h3));
        const int c = half * 4 + (j >> 1);
        const uint32_t soff = row * 128 + (((c ^ (row & 7))) << 4) + (j & 1) * 8;
        uint2 hp, lp;
        hp.x = pack2h(h0, h1); hp.y = pack2h(h2, h3);
        lp.x = pack2h(l0, l1); lp.y = pack2h(l2, l3);
        *(uint2*)(smem_raw + stoff + AH_OFF + soff) = hp;
        *(uint2*)(smem_raw + stoff + AL_OFF + soff) = lp;
    }
}

template <int FEAT>
__global__ __launch_bounds__(256, 1) void gemm_mma(const float* __restrict__ A,
                                                   const __half* __restrict__ Bh,
                                                   const float* __restrict__ bias,
                                                   float* __restrict__ C)
{
    extern __shared__ char smem_raw[];
    const uint32_t sb = smem_u32(smem_raw);

    const int tid = threadIdx.x;
    const int lane = tid & 31;
    const int wid = tid >> 5;
    const int wm = wid >> 2;
    const int wn = wid & 3;
    const int bm = blockIdx.y * 128;
    const int bn = blockIdx.x * 256;

    float acc[4][8][4];
#pragma unroll
    for (int i = 0; i < 4; i++)
#pragma unroll
        for (int j = 0; j < 8; j++)
#pragma unroll
            for (int q = 0; q < 4; q++) acc[i][j][q] = 0.f;

    // prologue: chunk 0 loads + convert
    issue_loads(sb, A, Bh, bm, bn, 0, tid);
    CP_WAIT(1);                 // rawA(0) done (B(0) may be pending)
    __syncthreads();
    convert_A(smem_raw, 0, tid);

#pragma unroll 1
    for (int ch = 0; ch < 8; ch++) {
        const uint32_t cur = (ch & 1) * STAGE_SZ;
        const uint32_t nxt = ((ch + 1) & 1) * STAGE_SZ;

        if (ch < 7) {
            issue_loads(sb + nxt, A, Bh, bm, bn, ch + 1, tid);
            CP_WAIT(1);         // rawA(ch+1) + B(ch) done; B(ch+1) pending
        } else {
            CP_WAIT(0);
        }
        __syncthreads();        // convert STS (ch) visible; buffers settled

        const uint32_t sAh = sb + cur + AH_OFF;
        const uint32_t sAl = sb + cur + AL_OFF;
        const uint32_t sB  = sb + cur + B_OFF;

#pragma unroll
        for (int s16 = 0; s16 < 4; s16++) {
            uint32_t ah[4][4], al[4][4];
#pragma unroll
            for (int mf = 0; mf < 4; mf++) {
                const int arow = wm * 64 + mf * 16 + (lane & 15);
                const int achk = s16 * 2 + (lane >> 4);
                const uint32_t aoff = arow * 128 + ((achk ^ (arow & 7)) << 4);
                LDSM4(ah[mf], sAh + aoff);
                LDSM4(al[mf], sAl + aoff);
            }
#pragma unroll
            for (int nf = 0; nf < 4; nf++) {
                uint32_t bh[4];
                const int brow = wn * 64 + nf * 16 + (lane & 7) + ((lane >> 4) << 3);
                const int bchk = s16 * 2 + ((lane >> 3) & 1);
                const uint32_t boff = brow * 128 + ((bchk ^ (brow & 7)) << 4);
                LDSM4(bh, sB + boff);
#pragma unroll
                for (int mf = 0; mf < 4; mf++) {
                    MMA16816(acc[mf][2 * nf],     ah[mf], bh[0], bh[1]);
                    MMA16816(acc[mf][2 * nf + 1], ah[mf], bh[2], bh[3]);
                }
#pragma unroll
                for (int mf = 0; mf < 4; mf++) {
                    MMA16816(acc[mf][2 * nf],     al[mf], bh[0], bh[1]);
                    MMA16816(acc[mf][2 * nf + 1], al[mf], bh[2], bh[3]);
                }
            }
        }

        if (ch < 7) convert_A(smem_raw, nxt, tid);   // fill fp16 A for ch+1
        __syncthreads();
    }

    // Epilogue: bias + optional elu+1.
#pragma unroll
    for (int mf = 0; mf < 4; mf++) {
        const int row0 = bm + wm * 64 + mf * 16 + (lane >> 2);
#pragma unroll
        for (int nf8 = 0; nf8 < 8; nf8++) {
            const int col = bn + wn * 64 + nf8 * 8 + (lane & 3) * 2;
            const float b0 = bias[col], b1 = bias[col + 1];
            float x0 = acc[mf][nf8][0] + b0;
            float x1 = acc[mf][nf8][1] + b1;
            float x2 = acc[mf][nf8][2] + b0;
            float x3 = acc[mf][nf8][3] + b1;
            if (FEAT) {
                x0 = (x0 > 0.f) ? (x0 + 1.f) : expf(x0);
                x1 = (x1 > 0.f) ? (x1 + 1.f) : expf(x1);
                x2 = (x2 > 0.f) ? (x2 + 1.f) : expf(x2);
                x3 = (x3 > 0.f) ? (x3 + 1.f) : expf(x3);
            }
            *(float2*)&C[(size_t)row0 * ED + col]       = make_float2(x0, x1);
            *(float2*)&C[(size_t)(row0 + 8) * ED + col] = make_float2(x2, x3);
        }
    }
}

// ---------------- small kernels ---------------------------------------------
__global__ void zero_small()
{
    int i = blockIdx.x * blockDim.x + threadIdx.x;
    if (i < NB * NH * DH * DH) g_kv[i] = 0.f;
    if (i < NB * NH * DH)      g_ksum[i] = 0.f;
}

__global__ __launch_bounds__(256) void kv_kernel()
{
    __shared__ float Ksh[32][64];
    __shared__ float Vsh[32][64];

    const int tid = threadIdx.x;
    const int sp = blockIdx.x;
    const int h = blockIdx.y;
    const int n = blockIdx.z;
    const int tx = tid & 15;
    const int ty = tid >> 4;
    const int s0 = sp * (SL / 8);

    float acc[4][4];
#pragma unroll
    for (int i = 0; i < 4; i++)
#pragma unroll
        for (int j = 0; j < 4; j++) acc[i][j] = 0.f;
    float ks = 0.f;

    for (int st = 0; st < SL / 8; st += 32) {
        __syncthreads();
#pragma unroll
        for (int t = tid; t < 512; t += 256) {
            const int r = t >> 4;
            const int c = (t & 15) * 4;
            const size_t g = ((size_t)(n * SL + s0 + st + r)) * ED + h * DH + c;
            *(float4*)&Ksh[r][c] = *(const float4*)&g_k[g];
            *(float4*)&Vsh[r][c] = *(const float4*)&g_v[g];
        }
        __syncthreads();
#pragma unroll 8
        for (int ss = 0; ss < 32; ss++) {
            float4 vm = *(const float4*)&Vsh[ss][ty * 4];
            float4 kd = *(const float4*)&Ksh[ss][tx * 4];
            const float a[4] = {vm.x, vm.y, vm.z, vm.w};
            const float b[4] = {kd.x, kd.y, kd.z, kd.w};
#pragma unroll
            for (int i = 0; i < 4; i++)
#pragma unroll
                for (int j = 0; j < 4; j++)
                    acc[i][j] = fmaf(a[i], b[j], acc[i][j]);
        }
        if (tid < 64) {
#pragma unroll 8
            for (int ss = 0; ss < 32; ss++) ks += Ksh[ss][tid];
        }
    }

    const int bse = (n * NH + h) * DH * DH;
#pragma unroll
    for (int i = 0; i < 4; i++)
#pragma unroll
        for (int j = 0; j < 4; j++)
            atomicAdd(&g_kv[bse + (ty * 4 + i) * DH + tx * 4 + j], acc[i][j]);
    if (tid < 64)
        atomicAdd(&g_ksum[(n * NH + h) * DH + tid], ks);
}

__global__ __launch_bounds__(256) void attn_kernel()
{
    __shared__ float Qs[64][65];
    __shared__ float KVs[64][65];
    __shared__ float Ksm[64];

    const int tid = threadIdx.x;
    const int lb = blockIdx.x * 64;
    const int h = blockIdx.y;
    const int n = blockIdx.z;
    const int tx = tid & 15;
    const int ty = tid >> 4;

    const int kvbase = (n * NH + h) * DH * DH;
    for (int t = tid; t < 4096; t += 256)
        KVs[t >> 6][t & 63] = g_kv[kvbase + t];
    for (int t = tid; t < 4096; t += 256) {
        const int l = t >> 6, d = t & 63;
        Qs[l][d] = g_q[((size_t)(n * SL + lb + l)) * ED + h * DH + d];
    }
    if (tid < 64) Ksm[tid] = g_ksum[(n * NH + h) * DH + tid];
    __syncthreads();

    float acc[4][4];
#pragma unroll
    for (int i = 0; i < 4; i++)
#pragma unroll
        for (int j = 0; j < 4; j++) acc[i][j] = 0.f;
    float z[4] = {0.f, 0.f, 0.f, 0.f};

#pragma unroll 4
    for (int d = 0; d < 64; d++) {
        float q[4], kv[4];
#pragma unroll
        for (int i = 0; i < 4; i++) q[i] = Qs[ty * 4 + i][d];
#pragma unroll
        for (int j = 0; j < 4; j++) kv[j] = KVs[tx * 4 + j][d];
        const float kd = Ksm[d];
#pragma unroll
        for (int i = 0; i < 4; i++) z[i] = fmaf(q[i], kd, z[i]);
#pragma unroll
        for (int i = 0; i < 4; i++)
#pragma unroll
            for (int j = 0; j < 4; j++)
                acc[i][j] = fmaf(q[i], kv[j], acc[i][j]);
    }

#pragma unroll
    for (int i = 0; i < 4; i++) {
        const float zi = 1.f / (z[i] + 1e-6f);
        const int l = lb + ty * 4 + i;
        const size_t ob = ((size_t)(n * SL + l)) * ED + h * DH + tx * 4;
        float4 o;
        o.x = acc[i][0] * zi; o.y = acc[i][1] * zi;
        o.z = acc[i][2] * zi; o.w = acc[i][3] * zi;
        *(float4*)&g_attn[ob] = o;
    }
}

// ---------------- launch -----------------------------------------------------
extern "C" void kernel_launch(void* const* d_in, const int* in_sizes, int n_in,
                              void* d_out, int out_size)
{
    const float* q_in = (const float*)d_in[0];
    const float* k_in = (const float*)d_in[1];
    const float* v_in = (const float*)d_in[2];
    const float* Wq = (const float*)d_in[3];
    const float* bq = (const float*)d_in[4];
    const float* Wk = (const float*)d_in[5];
    const float* bk = (const float*)d_in[6];
    const float* Wv = (const float*)d_in[7];
    const float* bv = (const float*)d_in[8];
    const float* Wo = (const float*)d_in[9];
    const float* bo = (const float*)d_in[10];
    float* out = (float*)d_out;

    float *pq, *pk, *pv, *pattn;
    __half* wh;
    cudaGetSymbolAddress((void**)&pq, g_q);
    cudaGetSymbolAddress((void**)&pk, g_k);
    cudaGetSymbolAddress((void**)&pv, g_v);
    cudaGetSymbolAddress((void**)&pattn, g_attn);
    cudaGetSymbolAddress((void**)&wh, g_wh);

    cudaFuncSetAttribute(gemm_mma<0>, cudaFuncAttributeMaxDynamicSharedMemorySize, GSMEM);
    cudaFuncSetAttribute(gemm_mma<1>, cudaFuncAttributeMaxDynamicSharedMemorySize, GSMEM);

    const int n4w = ED * ED / 4;
    dim3 blk(256);
    dim3 gsw((n4w + 255) / 256);
    dim3 gg(ED / 256, MT / 128);   // (2, 512)

    zero_small<<<(NB * NH * DH * DH + 255) / 256, 256>>>();

    wconv_kernel<<<gsw, blk>>>(Wq, wh, n4w);
    gemm_mma<1><<<gg, blk, GSMEM>>>(q_in, wh, bq, pq);

    wconv_kernel<<<gsw, blk>>>(Wk, wh, n4w);
    gemm_mma<1><<<gg, blk, GSMEM>>>(k_in, wh, bk, pk);

    wconv_kernel<<<gsw, blk>>>(Wv, wh, n4w);
    gemm_mma<0><<<gg, blk, GSMEM>>>(v_in, wh, bv, pv);

    kv_kernel<<<dim3(8, NH, NB), blk>>>();
    attn_kernel<<<dim3(SL / 64, NH, NB), blk>>>();

    wconv_kernel<<<gsw, blk>>>(Wo, wh, n4w);
    gemm_mma<0><<<gg, blk, GSMEM>>>(pattn, wh, bo, out);
}

// round 5
// speedup vs baseline: 2.7664x; 1.1792x over previous
#include <cuda_runtime.h>
#include <cuda_fp16.h>
#include <math.h>
#include <stdint.h>

#define NB 8
#define SL 8192
#define ED 512
#define NH 8
#define DH 64
#define MT (NB*SL)

// ---------------- scratch (device globals; no allocation allowed) ----------
__device__ float g_q[(size_t)MT * ED];
__device__ float g_k[(size_t)MT * ED];
__device__ float g_v[(size_t)MT * ED];
__device__ float g_kv[NB * NH * DH * DH];
__device__ float g_ksum[NB * NH * DH];
__device__ __half g_xh[(size_t)MT * ED];   // A hi (fp16)
__device__ __half g_xl[(size_t)MT * ED];   // A lo (fp16)
__device__ __half g_wh[ED * ED];           // W fp16

// ---------------- helpers ---------------------------------------------------
__device__ __forceinline__ uint32_t smem_u32(const void* p) {
    uint32_t a;
    asm("{ .reg .u64 t; cvta.to.shared.u64 t, %1; cvt.u32.u64 %0, t; }" : "=r"(a) : "l"(p));
    return a;
}
__device__ __forceinline__ uint32_t pack2h(__half a, __half b) {
    __half2 t(a, b);
    return *reinterpret_cast<uint32_t*>(&t);
}
__device__ __forceinline__ void cp16(uint32_t s, const void* g) {
    asm volatile("cp.async.cg.shared.global [%0], [%1], 16;" :: "r"(s), "l"(g));
}
#define CP_COMMIT() asm volatile("cp.async.commit_group;" ::: "memory")
#define CP_WAIT(N)  asm volatile("cp.async.wait_group %0;" :: "n"(N) : "memory")

#define LDSM4(r, addr)                                                         \
    asm volatile("ldmatrix.sync.aligned.m8n8.x4.shared.b16 {%0,%1,%2,%3}, [%4];" \
        : "=r"((r)[0]), "=r"((r)[1]), "=r"((r)[2]), "=r"((r)[3]) : "r"(addr))

#define MMA16816(d, a, b0, b1)                                                 \
    asm volatile("mma.sync.aligned.m16n8k16.row.col.f32.f16.f16.f32 "          \
        "{%0,%1,%2,%3}, {%4,%5,%6,%7}, {%8,%9}, {%0,%1,%2,%3};"                \
        : "+f"((d)[0]), "+f"((d)[1]), "+f"((d)[2]), "+f"((d)[3])               \
        : "r"((a)[0]), "r"((a)[1]), "r"((a)[2]), "r"((a)[3]), "r"(b0), "r"(b1))

// ---------------- split fp32 -> fp16 hi/lo -----------------------------------
__global__ __launch_bounds__(256) void split_kernel(const float* __restrict__ src,
                                                    __half* __restrict__ hi,
                                                    __half* __restrict__ lo, int n4)
{
    int i = blockIdx.x * blockDim.x + threadIdx.x;
    if (i >= n4) return;
    float4 v = ((const float4*)src)[i];
    __half h0 = __float2half_rn(v.x), h1 = __float2half_rn(v.y);
    __half h2 = __float2half_rn(v.z), h3 = __float2half_rn(v.w);
    __half l0 = __float2half_rn(v.x - __half2float(h0));
    __half l1 = __float2half_rn(v.y - __half2float(h1));
    __half l2 = __float2half_rn(v.z - __half2float(h2));
    __half l3 = __float2half_rn(v.w - __half2float(h3));
    uint2 hp, lp;
    hp.x = pack2h(h0, h1); hp.y = pack2h(h2, h3);
    lp.x = pack2h(l0, l1); lp.y = pack2h(l2, l3);
    ((uint2*)hi)[i] = hp;
    ((uint2*)lo)[i] = lp;
}

__global__ __launch_bounds__(256) void wconv_kernel(const float* __restrict__ src,
                                                    __half* __restrict__ dst, int n4)
{
    int i = blockIdx.x * blockDim.x + threadIdx.x;
    if (i >= n4) return;
    float4 v = ((const float4*)src)[i];
    uint2 p;
    p.x = pack2h(__float2half_rn(v.x), __float2half_rn(v.y));
    p.y = pack2h(__float2half_rn(v.z), __float2half_rn(v.w));
    ((uint2*)dst)[i] = p;
}

// ---------------- fp16 2-term GEMM, 512 threads, pipelined fragments ---------
// C[M,512] = (Ah+Al)[M,512] @ Wh[512,512]^T + bias; FEAT -> elu+1.
// CTA 128x256, 16 warps of 32x64. BK=64, smem double-buffered.
#define AH_OFF   0
#define AL_OFF   16384
#define B_OFF    32768
#define STAGE_SZ 65536
#define GSMEM    (2 * STAGE_SZ)

__device__ __forceinline__ void issue_loads(uint32_t st,
                                            const __half* __restrict__ Ah,
                                            const __half* __restrict__ Al,
                                            const __half* __restrict__ Bh,
                                            int bm, int bn, int ch, int tid)
{
    const int kc = ch * 64;
#pragma unroll
    for (int i = 0; i < 2; i++) {
        const int idx = tid + i * 512;          // 0..1023
        const int row = idx >> 3;               // 0..127
        const int c = idx & 7;
        const uint32_t soff = row * 128 + ((c ^ (row & 7)) << 4);
        const size_t goff = (size_t)(bm + row) * ED + kc + c * 8;
        cp16(st + AH_OFF + soff, Ah + goff);
        cp16(st + AL_OFF + soff, Al + goff);
    }
#pragma unroll
    for (int i = 0; i < 4; i++) {
        const int idx = tid + i * 512;          // 0..2047
        const int row = idx >> 3;               // 0..255
        const int c = idx & 7;
        cp16(st + B_OFF + row * 128 + ((c ^ (row & 7)) << 4),
             Bh + (size_t)(bn + row) * ED + kc + c * 8);
    }
    CP_COMMIT();
}

template <int FEAT>
__global__ __launch_bounds__(512, 1) void gemm_mma(const __half* __restrict__ Ah,
                                                   const __half* __restrict__ Al,
                                                   const __half* __restrict__ Bh,
                                                   const float* __restrict__ bias,
                                                   float* __restrict__ C)
{
    extern __shared__ char smem_raw[];
    const uint32_t sb = smem_u32(smem_raw);

    const int tid = threadIdx.x;
    const int lane = tid & 31;
    const int wid = tid >> 5;         // 0..15
    const int wm = wid >> 2;          // 0..3  (32-row band)
    const int wn = wid & 3;           // 0..3  (64-col band)
    const int bm = blockIdx.y * 128;
    const int bn = blockIdx.x * 256;

    float acc[2][8][4];
#pragma unroll
    for (int i = 0; i < 2; i++)
#pragma unroll
        for (int j = 0; j < 8; j++)
#pragma unroll
            for (int q = 0; q < 4; q++) acc[i][j][q] = 0.f;

    issue_loads(sb, Ah, Al, Bh, bm, bn, 0, tid);

#pragma unroll 1
    for (int ch = 0; ch < 8; ch++) {
        const uint32_t cur = sb + (ch & 1) * STAGE_SZ;

        if (ch < 7) {
            issue_loads(sb + ((ch + 1) & 1) * STAGE_SZ, Ah, Al, Bh, bm, bn, ch + 1, tid);
            CP_WAIT(1);
        } else {
            CP_WAIT(0);
        }
        __syncthreads();

        const uint32_t sAh = cur + AH_OFF;
        const uint32_t sAl = cur + AL_OFF;
        const uint32_t sB  = cur + B_OFF;

        uint32_t fa[2][2][2][4];   // [buf][mf][hi/lo][4]
        uint32_t fb[2][4];         // [buf][4]

        // fragment address helpers (compile-time unrolled lambdas)
        #define LOAD_A(s16, buf)                                               \
        {                                                                      \
            _Pragma("unroll")                                                  \
            for (int mf = 0; mf < 2; mf++) {                                   \
                const int arow = wm * 32 + mf * 16 + (lane & 15);              \
                const int achk = (s16) * 2 + (lane >> 4);                      \
                const uint32_t aoff = arow * 128 + ((achk ^ (arow & 7)) << 4); \
                LDSM4(fa[buf][mf][0], sAh + aoff);                             \
                LDSM4(fa[buf][mf][1], sAl + aoff);                             \
            }                                                                  \
        }
        #define LOAD_B(s16, nf, buf)                                           \
        {                                                                       \
            const int brow = wn * 64 + (nf) * 16 + (lane & 7) + ((lane >> 4) << 3); \
            const int bchk = (s16) * 2 + ((lane >> 3) & 1);                    \
            LDSM4(fb[buf], sB + brow * 128 + ((bchk ^ (brow & 7)) << 4));      \
        }

        LOAD_A(0, 0);
        LOAD_B(0, 0, 0);

#pragma unroll
        for (int s16 = 0; s16 < 4; s16++) {
            const int ab = s16 & 1;
#pragma unroll
            for (int nf = 0; nf < 4; nf++) {
                const int bb = nf & 1;
                if (nf < 3) {
                    LOAD_B(s16, nf + 1, bb ^ 1);
                } else if (s16 < 3) {
                    LOAD_A(s16 + 1, ab ^ 1);
                    LOAD_B(s16 + 1, 0, bb ^ 1);
                }
#pragma unroll
                for (int mf = 0; mf < 2; mf++) {
                    MMA16816(acc[mf][2 * nf],     fa[ab][mf][0], fb[bb][0], fb[bb][1]);
                    MMA16816(acc[mf][2 * nf + 1], fa[ab][mf][0], fb[bb][2], fb[bb][3]);
                }
#pragma unroll
                for (int mf = 0; mf < 2; mf++) {
                    MMA16816(acc[mf][2 * nf],     fa[ab][mf][1], fb[bb][0], fb[bb][1]);
                    MMA16816(acc[mf][2 * nf + 1], fa[ab][mf][1], fb[bb][2], fb[bb][3]);
                }
            }
        }
        #undef LOAD_A
        #undef LOAD_B
        __syncthreads();
    }

    // Epilogue: bias + optional elu+1.
#pragma unroll
    for (int mf = 0; mf < 2; mf++) {
        const int row0 = bm + wm * 32 + mf * 16 + (lane >> 2);
#pragma unroll
        for (int nf8 = 0; nf8 < 8; nf8++) {
            const int col = bn + wn * 64 + nf8 * 8 + (lane & 3) * 2;
            const float b0 = bias[col], b1 = bias[col + 1];
            float x0 = acc[mf][nf8][0] + b0;
            float x1 = acc[mf][nf8][1] + b1;
            float x2 = acc[mf][nf8][2] + b0;
            float x3 = acc[mf][nf8][3] + b1;
            if (FEAT) {
                x0 = (x0 > 0.f) ? (x0 + 1.f) : expf(x0);
                x1 = (x1 > 0.f) ? (x1 + 1.f) : expf(x1);
                x2 = (x2 > 0.f) ? (x2 + 1.f) : expf(x2);
                x3 = (x3 > 0.f) ? (x3 + 1.f) : expf(x3);
            }
            *(float2*)&C[(size_t)row0 * ED + col]       = make_float2(x0, x1);
            *(float2*)&C[(size_t)(row0 + 8) * ED + col] = make_float2(x2, x3);
        }
    }
}

// ---------------- small kernels ---------------------------------------------
__global__ void zero_small()
{
    int i = blockIdx.x * blockDim.x + threadIdx.x;
    if (i < NB * NH * DH * DH) g_kv[i] = 0.f;
    if (i < NB * NH * DH)      g_ksum[i] = 0.f;
}

__global__ __launch_bounds__(256) void kv_kernel()
{
    __shared__ float Ksh[32][64];
    __shared__ float Vsh[32][64];

    const int tid = threadIdx.x;
    const int sp = blockIdx.x;
    const int h = blockIdx.y;
    const int n = blockIdx.z;
    const int tx = tid & 15;
    const int ty = tid >> 4;
    const int s0 = sp * (SL / 8);

    float acc[4][4];
#pragma unroll
    for (int i = 0; i < 4; i++)
#pragma unroll
        for (int j = 0; j < 4; j++) acc[i][j] = 0.f;
    float ks = 0.f;

    for (int st = 0; st < SL / 8; st += 32) {
        __syncthreads();
#pragma unroll
        for (int t = tid; t < 512; t += 256) {
            const int r = t >> 4;
            const int c = (t & 15) * 4;
            const size_t g = ((size_t)(n * SL + s0 + st + r)) * ED + h * DH + c;
            *(float4*)&Ksh[r][c] = *(const float4*)&g_k[g];
            *(float4*)&Vsh[r][c] = *(const float4*)&g_v[g];
        }
        __syncthreads();
#pragma unroll 8
        for (int ss = 0; ss < 32; ss++) {
            float4 vm = *(const float4*)&Vsh[ss][ty * 4];
            float4 kd = *(const float4*)&Ksh[ss][tx * 4];
            const float a[4] = {vm.x, vm.y, vm.z, vm.w};
            const float b[4] = {kd.x, kd.y, kd.z, kd.w};
#pragma unroll
            for (int i = 0; i < 4; i++)
#pragma unroll
                for (int j = 0; j < 4; j++)
                    acc[i][j] = fmaf(a[i], b[j], acc[i][j]);
        }
        if (tid < 64) {
#pragma unroll 8
            for (int ss = 0; ss < 32; ss++) ks += Ksh[ss][tid];
        }
    }

    const int bse = (n * NH + h) * DH * DH;
#pragma unroll
    for (int i = 0; i < 4; i++)
#pragma unroll
        for (int j = 0; j < 4; j++)
            atomicAdd(&g_kv[bse + (ty * 4 + i) * DH + tx * 4 + j], acc[i][j]);
    if (tid < 64)
        atomicAdd(&g_ksum[(n * NH + h) * DH + tid], ks);
}

// writes fp16 hi/lo directly (input to final GEMM)
__global__ __launch_bounds__(256) void attn_kernel()
{
    __shared__ float Qs[64][65];
    __shared__ float KVs[64][65];
    __shared__ float Ksm[64];

    const int tid = threadIdx.x;
    const int lb = blockIdx.x * 64;
    const int h = blockIdx.y;
    const int n = blockIdx.z;
    const int tx = tid & 15;
    const int ty = tid >> 4;

    const int kvbase = (n * NH + h) * DH * DH;
    for (int t = tid; t < 4096; t += 256)
        KVs[t >> 6][t & 63] = g_kv[kvbase + t];
    for (int t = tid; t < 4096; t += 256) {
        const int l = t >> 6, d = t & 63;
        Qs[l][d] = g_q[((size_t)(n * SL + lb + l)) * ED + h * DH + d];
    }
    if (tid < 64) Ksm[tid] = g_ksum[(n * NH + h) * DH + tid];
    __syncthreads();

    float acc[4][4];
#pragma unroll
    for (int i = 0; i < 4; i++)
#pragma unroll
        for (int j = 0; j < 4; j++) acc[i][j] = 0.f;
    float z[4] = {0.f, 0.f, 0.f, 0.f};

#pragma unroll 4
    for (int d = 0; d < 64; d++) {
        float q[4], kv[4];
#pragma unroll
        for (int i = 0; i < 4; i++) q[i] = Qs[ty * 4 + i][d];
#pragma unroll
        for (int j = 0; j < 4; j++) kv[j] = KVs[tx * 4 + j][d];
        const float kd = Ksm[d];
#pragma unroll
        for (int i = 0; i < 4; i++) z[i] = fmaf(q[i], kd, z[i]);
#pragma unroll
        for (int i = 0; i < 4; i++)
#pragma unroll
            for (int j = 0; j < 4; j++)
                acc[i][j] = fmaf(q[i], kv[j], acc[i][j]);
    }

#pragma unroll
    for (int i = 0; i < 4; i++) {
        const float zi = 1.f / (z[i] + 1e-6f);
        const int l = lb + ty * 4 + i;
        const size_t ob = ((size_t)(n * SL + l)) * ED + h * DH + tx * 4;
        float o0 = acc[i][0] * zi, o1 = acc[i][1] * zi;
        float o2 = acc[i][2] * zi, o3 = acc[i][3] * zi;
        __half h0 = __float2half_rn(o0), h1 = __float2half_rn(o1);
        __half h2 = __float2half_rn(o2), h3 = __float2half_rn(o3);
        __half l0 = __float2half_rn(o0 - __half2float(h0));
        __half l1 = __float2half_rn(o1 - __half2float(h1));
        __half l2 = __float2half_rn(o2 - __half2float(h2));
        __half l3 = __float2half_rn(o3 - __half2float(h3));
        uint2 hp, lp;
        hp.x = pack2h(h0, h1); hp.y = pack2h(h2, h3);
        lp.x = pack2h(l0, l1); lp.y = pack2h(l2, l3);
        *(uint2*)&g_xh[ob] = hp;
        *(uint2*)&g_xl[ob] = lp;
    }
}

// ---------------- launch -----------------------------------------------------
extern "C" void kernel_launch(void* const* d_in, const int* in_sizes, int n_in,
                              void* d_out, int out_size)
{
    const float* q_in = (const float*)d_in[0];
    const float* k_in = (const float*)d_in[1];
    const float* v_in = (const float*)d_in[2];
    const float* Wq = (const float*)d_in[3];
    const float* bq = (const float*)d_in[4];
    const float* Wk = (const float*)d_in[5];
    const float* bk = (const float*)d_in[6];
    const float* Wv = (const float*)d_in[7];
    const float* bv = (const float*)d_in[8];
    const float* Wo = (const float*)d_in[9];
    const float* bo = (const float*)d_in[10];
    float* out = (float*)d_out;

    float *pq, *pk, *pv;
    __half *xh, *xl, *wh;
    cudaGetSymbolAddress((void**)&pq, g_q);
    cudaGetSymbolAddress((void**)&pk, g_k);
    cudaGetSymbolAddress((void**)&pv, g_v);
    cudaGetSymbolAddress((void**)&xh, g_xh);
    cudaGetSymbolAddress((void**)&xl, g_xl);
    cudaGetSymbolAddress((void**)&wh, g_wh);

    cudaFuncSetAttribute(gemm_mma<0>, cudaFuncAttributeMaxDynamicSharedMemorySize, GSMEM);
    cudaFuncSetAttribute(gemm_mma<1>, cudaFuncAttributeMaxDynamicSharedMemorySize, GSMEM);

    const int n4x = (int)((size_t)MT * ED / 4);
    const int n4w = ED * ED / 4;
    dim3 blk(256);
    dim3 gblk(512);
    dim3 gsx((n4x + 255) / 256);
    dim3 gsw((n4w + 255) / 256);
    dim3 gg(ED / 256, MT / 128);   // (2, 512)

    zero_small<<<(NB * NH * DH * DH + 255) / 256, 256>>>();

    split_kernel<<<gsx, blk>>>(q_in, xh, xl, n4x);
    wconv_kernel<<<gsw, blk>>>(Wq, wh, n4w);
    gemm_mma<1><<<gg, gblk, GSMEM>>>(xh, xl, wh, bq, pq);

    split_kernel<<<gsx, blk>>>(k_in, xh, xl, n4x);
    wconv_kernel<<<gsw, blk>>>(Wk, wh, n4w);
    gemm_mma<1><<<gg, gblk, GSMEM>>>(xh, xl, wh, bk, pk);

    split_kernel<<<gsx, blk>>>(v_in, xh, xl, n4x);
    wconv_kernel<<<gsw, blk>>>(Wv, wh, n4w);
    gemm_mma<0><<<gg, gblk, GSMEM>>>(xh, xl, wh, bv, pv);

    kv_kernel<<<dim3(8, NH, NB), blk>>>();
    attn_kernel<<<dim3(SL / 64, NH, NB), blk>>>();

    wconv_kernel<<<gsw, blk>>>(Wo, wh, n4w);
    gemm_mma<0><<<gg, gblk, GSMEM>>>(xh, xl, wh, bo, out);
}

// round 6
// speedup vs baseline: 2.8497x; 1.0301x over previous
#include <cuda_runtime.h>
#include <cuda_fp16.h>
#include <math.h>
#include <stdint.h>

#define NB 8
#define SL 8192
#define ED 512
#define NH 8
#define DH 64
#define MT (NB*SL)

// ---------------- scratch (device globals; no allocation allowed) ----------
__device__ float g_q[(size_t)MT * ED];
__device__ float g_k[(size_t)MT * ED];
__device__ float g_v[(size_t)MT * ED];
__device__ float g_kv[NB * NH * DH * DH];
__device__ float g_ksum[NB * NH * DH];
// input splits (separate per tensor so they can be produced concurrently)
__device__ __half g_xqh[(size_t)MT * ED];
__device__ __half g_xql[(size_t)MT * ED];
__device__ __half g_xkh[(size_t)MT * ED];
__device__ __half g_xkl[(size_t)MT * ED];
__device__ __half g_xvh[(size_t)MT * ED];
__device__ __half g_xvl[(size_t)MT * ED];
// attn output splits (input to final GEMM)
__device__ __half g_aoh[(size_t)MT * ED];
__device__ __half g_aol[(size_t)MT * ED];
// fp16 weights
__device__ __half g_w16[4][ED * ED];

// ---------------- helpers ---------------------------------------------------
__device__ __forceinline__ uint32_t smem_u32(const void* p) {
    uint32_t a;
    asm("{ .reg .u64 t; cvta.to.shared.u64 t, %1; cvt.u32.u64 %0, t; }" : "=r"(a) : "l"(p));
    return a;
}
__device__ __forceinline__ uint32_t pack2h(__half a, __half b) {
    __half2 t(a, b);
    return *reinterpret_cast<uint32_t*>(&t);
}
__device__ __forceinline__ void cp16(uint32_t s, const void* g) {
    asm volatile("cp.async.cg.shared.global [%0], [%1], 16;" :: "r"(s), "l"(g));
}
#define CP_COMMIT() asm volatile("cp.async.commit_group;" ::: "memory")
#define CP_WAIT(N)  asm volatile("cp.async.wait_group %0;" :: "n"(N) : "memory")

#define LDSM4(r, addr)                                                         \
    asm volatile("ldmatrix.sync.aligned.m8n8.x4.shared.b16 {%0,%1,%2,%3}, [%4];" \
        : "=r"((r)[0]), "=r"((r)[1]), "=r"((r)[2]), "=r"((r)[3]) : "r"(addr))

#define MMA16816(d, a, b0, b1)                                                 \
    asm volatile("mma.sync.aligned.m16n8k16.row.col.f32.f16.f16.f32 "          \
        "{%0,%1,%2,%3}, {%4,%5,%6,%7}, {%8,%9}, {%0,%1,%2,%3};"                \
        : "+f"((d)[0]), "+f"((d)[1]), "+f"((d)[2]), "+f"((d)[3])               \
        : "r"((a)[0]), "r"((a)[1]), "r"((a)[2]), "r"((a)[3]), "r"(b0), "r"(b1))

// ---------------- split fp32 -> fp16 hi/lo -----------------------------------
__global__ __launch_bounds__(256) void split_kernel(const float* __restrict__ src,
                                                    __half* __restrict__ hi,
                                                    __half* __restrict__ lo, int n4)
{
    int i = blockIdx.x * blockDim.x + threadIdx.x;
    if (i >= n4) return;
    float4 v = ((const float4*)src)[i];
    __half h0 = __float2half_rn(v.x), h1 = __float2half_rn(v.y);
    __half h2 = __float2half_rn(v.z), h3 = __float2half_rn(v.w);
    __half l0 = __float2half_rn(v.x - __half2float(h0));
    __half l1 = __float2half_rn(v.y - __half2float(h1));
    __half l2 = __float2half_rn(v.z - __half2float(h2));
    __half l3 = __float2half_rn(v.w - __half2float(h3));
    uint2 hp, lp;
    hp.x = pack2h(h0, h1); hp.y = pack2h(h2, h3);
    lp.x = pack2h(l0, l1); lp.y = pack2h(l2, l3);
    ((uint2*)hi)[i] = hp;
    ((uint2*)lo)[i] = lp;
}

__global__ __launch_bounds__(256) void wconv_kernel(const float* __restrict__ src,
                                                    __half* __restrict__ dst, int n4)
{
    int i = blockIdx.x * blockDim.x + threadIdx.x;
    if (i >= n4) return;
    float4 v = ((const float4*)src)[i];
    uint2 p;
    p.x = pack2h(__float2half_rn(v.x), __float2half_rn(v.y));
    p.y = pack2h(__float2half_rn(v.z), __float2half_rn(v.w));
    ((uint2*)dst)[i] = p;
}

// ---------------- fp16 2-term GEMM, 256 thr, 2 CTAs/SM -----------------------
// C[M,512] = (Ah+Al)[M,512] @ Wh[512,512]^T + bias; FEAT -> elu+1.
// CTA 128x128, 8 warps of 32x64. BK=64, smem double-buffered (2 x 48KB).
#define AH_OFF   0
#define AL_OFF   16384
#define B_OFF    32768
#define STAGE_SZ 49152
#define GSMEM    (2 * STAGE_SZ)

__device__ __forceinline__ void issue_loads(uint32_t st,
                                            const __half* __restrict__ Ah,
                                            const __half* __restrict__ Al,
                                            const __half* __restrict__ Bh,
                                            int bm, int bn, int ch, int tid)
{
    const int kc = ch * 64;
#pragma unroll
    for (int i = 0; i < 4; i++) {
        const int idx = tid + i * 256;          // 0..1023
        const int row = idx >> 3;               // 0..127
        const int c = idx & 7;
        const uint32_t soff = row * 128 + ((c ^ (row & 7)) << 4);
        const size_t goff = (size_t)(bm + row) * ED + kc + c * 8;
        cp16(st + AH_OFF + soff, Ah + goff);
        cp16(st + AL_OFF + soff, Al + goff);
        cp16(st + B_OFF + soff, Bh + (size_t)(bn + row) * ED + kc + c * 8);
    }
    CP_COMMIT();
}

template <int FEAT>
__global__ __launch_bounds__(256, 2) void gemm_mma(const __half* __restrict__ Ah,
                                                   const __half* __restrict__ Al,
                                                   const __half* __restrict__ Bh,
                                                   const float* __restrict__ bias,
                                                   float* __restrict__ C)
{
    extern __shared__ char smem_raw[];
    const uint32_t sb = smem_u32(smem_raw);

    const int tid = threadIdx.x;
    const int lane = tid & 31;
    const int wid = tid >> 5;         // 0..7
    const int wm = wid >> 1;          // 0..3  (32-row band)
    const int wn = wid & 1;           // 0..1  (64-col band)
    const int bm = blockIdx.y * 128;
    const int bn = blockIdx.x * 128;

    float acc[2][8][4];
#pragma unroll
    for (int i = 0; i < 2; i++)
#pragma unroll
        for (int j = 0; j < 8; j++)
#pragma unroll
            for (int q = 0; q < 4; q++) acc[i][j][q] = 0.f;

    issue_loads(sb, Ah, Al, Bh, bm, bn, 0, tid);

#pragma unroll 1
    for (int ch = 0; ch < 8; ch++) {
        const uint32_t cur = sb + (ch & 1) * STAGE_SZ;

        if (ch < 7) {
            issue_loads(sb + ((ch + 1) & 1) * STAGE_SZ, Ah, Al, Bh, bm, bn, ch + 1, tid);
            CP_WAIT(1);
        } else {
            CP_WAIT(0);
        }
        __syncthreads();

        const uint32_t sAh = cur + AH_OFF;
        const uint32_t sAl = cur + AL_OFF;
        const uint32_t sB  = cur + B_OFF;

        uint32_t fa[2][2][2][4];   // [buf][mf][hi/lo][4]
        uint32_t fb[2][4];         // [buf][4]

        #define LOAD_A(s16, buf)                                               \
        {                                                                      \
            _Pragma("unroll")                                                  \
            for (int mf = 0; mf < 2; mf++) {                                   \
                const int arow = wm * 32 + mf * 16 + (lane & 15);              \
                const int achk = (s16) * 2 + (lane >> 4);                      \
                const uint32_t aoff = arow * 128 + ((achk ^ (arow & 7)) << 4); \
                LDSM4(fa[buf][mf][0], sAh + aoff);                             \
                LDSM4(fa[buf][mf][1], sAl + aoff);                             \
            }                                                                  \
        }
        #define LOAD_B(s16, nf, buf)                                           \
        {                                                                       \
            const int brow = wn * 64 + (nf) * 16 + (lane & 7) + ((lane >> 4) << 3); \
            const int bchk = (s16) * 2 + ((lane >> 3) & 1);                    \
            LDSM4(fb[buf], sB + brow * 128 + ((bchk ^ (brow & 7)) << 4));      \
        }

        LOAD_A(0, 0);
        LOAD_B(0, 0, 0);

#pragma unroll
        for (int s16 = 0; s16 < 4; s16++) {
            const int ab = s16 & 1;
#pragma unroll
            for (int nf = 0; nf < 4; nf++) {
                const int bb = nf & 1;
                if (nf < 3) {
                    LOAD_B(s16, nf + 1, bb ^ 1);
                } else if (s16 < 3) {
                    LOAD_A(s16 + 1, ab ^ 1);
                    LOAD_B(s16 + 1, 0, bb ^ 1);
                }
#pragma unroll
                for (int mf = 0; mf < 2; mf++) {
                    MMA16816(acc[mf][2 * nf],     fa[ab][mf][0], fb[bb][0], fb[bb][1]);
                    MMA16816(acc[mf][2 * nf + 1], fa[ab][mf][0], fb[bb][2], fb[bb][3]);
                }
#pragma unroll
                for (int mf = 0; mf < 2; mf++) {
                    MMA16816(acc[mf][2 * nf],     fa[ab][mf][1], fb[bb][0], fb[bb][1]);
                    MMA16816(acc[mf][2 * nf + 1], fa[ab][mf][1], fb[bb][2], fb[bb][3]);
                }
            }
        }
        #undef LOAD_A
        #undef LOAD_B
        __syncthreads();
    }

    // Epilogue: bias + optional elu+1.
#pragma unroll
    for (int mf = 0; mf < 2; mf++) {
        const int row0 = bm + wm * 32 + mf * 16 + (lane >> 2);
#pragma unroll
        for (int nf8 = 0; nf8 < 8; nf8++) {
            const int col = bn + wn * 64 + nf8 * 8 + (lane & 3) * 2;
            const float b0 = bias[col], b1 = bias[col + 1];
            float x0 = acc[mf][nf8][0] + b0;
            float x1 = acc[mf][nf8][1] + b1;
            float x2 = acc[mf][nf8][2] + b0;
            float x3 = acc[mf][nf8][3] + b1;
            if (FEAT) {
                x0 = (x0 > 0.f) ? (x0 + 1.f) : expf(x0);
                x1 = (x1 > 0.f) ? (x1 + 1.f) : expf(x1);
                x2 = (x2 > 0.f) ? (x2 + 1.f) : expf(x2);
                x3 = (x3 > 0.f) ? (x3 + 1.f) : expf(x3);
            }
            *(float2*)&C[(size_t)row0 * ED + col]       = make_float2(x0, x1);
            *(float2*)&C[(size_t)(row0 + 8) * ED + col] = make_float2(x2, x3);
        }
    }
}

// ---------------- small kernels ---------------------------------------------
__global__ void zero_small()
{
    int i = blockIdx.x * blockDim.x + threadIdx.x;
    if (i < NB * NH * DH * DH) g_kv[i] = 0.f;
    if (i < NB * NH * DH)      g_ksum[i] = 0.f;
}

__global__ __launch_bounds__(256) void kv_kernel()
{
    __shared__ float Ksh[32][64];
    __shared__ float Vsh[32][64];

    const int tid = threadIdx.x;
    const int sp = blockIdx.x;
    const int h = blockIdx.y;
    const int n = blockIdx.z;
    const int tx = tid & 15;
    const int ty = tid >> 4;
    const int s0 = sp * (SL / 8);

    float acc[4][4];
#pragma unroll
    for (int i = 0; i < 4; i++)
#pragma unroll
        for (int j = 0; j < 4; j++) acc[i][j] = 0.f;
    float ks = 0.f;

    for (int st = 0; st < SL / 8; st += 32) {
        __syncthreads();
#pragma unroll
        for (int t = tid; t < 512; t += 256) {
            const int r = t >> 4;
            const int c = (t & 15) * 4;
            const size_t g = ((size_t)(n * SL + s0 + st + r)) * ED + h * DH + c;
            *(float4*)&Ksh[r][c] = *(const float4*)&g_k[g];
            *(float4*)&Vsh[r][c] = *(const float4*)&g_v[g];
        }
        __syncthreads();
#pragma unroll 8
        for (int ss = 0; ss < 32; ss++) {
            float4 vm = *(const float4*)&Vsh[ss][ty * 4];
            float4 kd = *(const float4*)&Ksh[ss][tx * 4];
            const float a[4] = {vm.x, vm.y, vm.z, vm.w};
            const float b[4] = {kd.x, kd.y, kd.z, kd.w};
#pragma unroll
            for (int i = 0; i < 4; i++)
#pragma unroll
                for (int j = 0; j < 4; j++)
                    acc[i][j] = fmaf(a[i], b[j], acc[i][j]);
        }
        if (tid < 64) {
#pragma unroll 8
            for (int ss = 0; ss < 32; ss++) ks += Ksh[ss][tid];
        }
    }

    const int bse = (n * NH + h) * DH * DH;
#pragma unroll
    for (int i = 0; i < 4; i++)
#pragma unroll
        for (int j = 0; j < 4; j++)
            atomicAdd(&g_kv[bse + (ty * 4 + i) * DH + tx * 4 + j], acc[i][j]);
    if (tid < 64)
        atomicAdd(&g_ksum[(n * NH + h) * DH + tid], ks);
}

// writes fp16 hi/lo directly (input to final GEMM)
__global__ __launch_bounds__(256) void attn_kernel()
{
    __shared__ float Qs[64][65];
    __shared__ float KVs[64][65];
    __shared__ float Ksm[64];

    const int tid = threadIdx.x;
    const int lb = blockIdx.x * 64;
    const int h = blockIdx.y;
    const int n = blockIdx.z;
    const int tx = tid & 15;
    const int ty = tid >> 4;

    const int kvbase = (n * NH + h) * DH * DH;
    for (int t = tid; t < 4096; t += 256)
        KVs[t >> 6][t & 63] = g_kv[kvbase + t];
    for (int t = tid; t < 4096; t += 256) {
        const int l = t >> 6, d = t & 63;
        Qs[l][d] = g_q[((size_t)(n * SL + lb + l)) * ED + h * DH + d];
    }
    if (tid < 64) Ksm[tid] = g_ksum[(n * NH + h) * DH + tid];
    __syncthreads();

    float acc[4][4];
#pragma unroll
    for (int i = 0; i < 4; i++)
#pragma unroll
        for (int j = 0; j < 4; j++) acc[i][j] = 0.f;
    float z[4] = {0.f, 0.f, 0.f, 0.f};

#pragma unroll 4
    for (int d = 0; d < 64; d++) {
        float q[4], kv[4];
#pragma unroll
        for (int i = 0; i < 4; i++) q[i] = Qs[ty * 4 + i][d];
#pragma unroll
        for (int j = 0; j < 4; j++) kv[j] = KVs[tx * 4 + j][d];
        const float kd = Ksm[d];
#pragma unroll
        for (int i = 0; i < 4; i++) z[i] = fmaf(q[i], kd, z[i]);
#pragma unroll
        for (int i = 0; i < 4; i++)
#pragma unroll
            for (int j = 0; j < 4; j++)
                acc[i][j] = fmaf(q[i], kv[j], acc[i][j]);
    }

#pragma unroll
    for (int i = 0; i < 4; i++) {
        const float zi = 1.f / (z[i] + 1e-6f);
        const int l = lb + ty * 4 + i;
        const size_t ob = ((size_t)(n * SL + l)) * ED + h * DH + tx * 4;
        float o0 = acc[i][0] * zi, o1 = acc[i][1] * zi;
        float o2 = acc[i][2] * zi, o3 = acc[i][3] * zi;
        __half h0 = __float2half_rn(o0), h1 = __float2half_rn(o1);
        __half h2 = __float2half_rn(o2), h3 = __float2half_rn(o3);
        __half l0 = __float2half_rn(o0 - __half2float(h0));
        __half l1 = __float2half_rn(o1 - __half2float(h1));
        __half l2 = __float2half_rn(o2 - __half2float(h2));
        __half l3 = __float2half_rn(o3 - __half2float(h3));
        uint2 hp, lp;
        hp.x = pack2h(h0, h1); hp.y = pack2h(h2, h3);
        lp.x = pack2h(l0, l1); lp.y = pack2h(l2, l3);
        *(uint2*)&g_aoh[ob] = hp;
        *(uint2*)&g_aol[ob] = lp;
    }
}

// ---------------- launch -----------------------------------------------------
extern "C" void kernel_launch(void* const* d_in, const int* in_sizes, int n_in,
                              void* d_out, int out_size)
{
    const float* q_in = (const float*)d_in[0];
    const float* k_in = (const float*)d_in[1];
    const float* v_in = (const float*)d_in[2];
    const float* Wq = (const float*)d_in[3];
    const float* bq = (const float*)d_in[4];
    const float* Wk = (const float*)d_in[5];
    const float* bk = (const float*)d_in[6];
    const float* Wv = (const float*)d_in[7];
    const float* bv = (const float*)d_in[8];
    const float* Wo = (const float*)d_in[9];
    const float* bo = (const float*)d_in[10];
    float* out = (float*)d_out;

    float *pq, *pk, *pv;
    __half *xqh, *xql, *xkh, *xkl, *xvh, *xvl, *aoh, *aol, *w16;
    cudaGetSymbolAddress((void**)&pq, g_q);
    cudaGetSymbolAddress((void**)&pk, g_k);
    cudaGetSymbolAddress((void**)&pv, g_v);
    cudaGetSymbolAddress((void**)&xqh, g_xqh);
    cudaGetSymbolAddress((void**)&xql, g_xql);
    cudaGetSymbolAddress((void**)&xkh, g_xkh);
    cudaGetSymbolAddress((void**)&xkl, g_xkl);
    cudaGetSymbolAddress((void**)&xvh, g_xvh);
    cudaGetSymbolAddress((void**)&xvl, g_xvl);
    cudaGetSymbolAddress((void**)&aoh, g_aoh);
    cudaGetSymbolAddress((void**)&aol, g_aol);
    cudaGetSymbolAddress((void**)&w16, g_w16);
    __half* wq16 = w16;
    __half* wk16 = w16 + (size_t)ED * ED;
    __half* wv16 = w16 + (size_t)2 * ED * ED;
    __half* wo16 = w16 + (size_t)3 * ED * ED;

    static cudaStream_t s1, s2, s3;
    static cudaEvent_t ev0, evSK, evSV, evW;
    static bool inited = false;
    if (!inited) {
        cudaStreamCreateWithFlags(&s1, cudaStreamNonBlocking);
        cudaStreamCreateWithFlags(&s2, cudaStreamNonBlocking);
        cudaStreamCreateWithFlags(&s3, cudaStreamNonBlocking);
        cudaEventCreateWithFlags(&ev0, cudaEventDisableTiming);
        cudaEventCreateWithFlags(&evSK, cudaEventDisableTiming);
        cudaEventCreateWithFlags(&evSV, cudaEventDisableTiming);
        cudaEventCreateWithFlags(&evW, cudaEventDisableTiming);
        inited = true;
    }

    cudaFuncSetAttribute(gemm_mma<0>, cudaFuncAttributeMaxDynamicSharedMemorySize, GSMEM);
    cudaFuncSetAttribute(gemm_mma<1>, cudaFuncAttributeMaxDynamicSharedMemorySize, GSMEM);

    const int n4x = (int)((size_t)MT * ED / 4);
    const int n4w = ED * ED / 4;
    dim3 blk(256);
    dim3 gsx((n4x + 255) / 256);
    dim3 gsw((n4w + 255) / 256);
    dim3 gg(ED / 128, MT / 128);   // (4, 512)

    // fork
    cudaEventRecord(ev0, 0);
    cudaStreamWaitEvent(s1, ev0, 0);
    cudaStreamWaitEvent(s2, ev0, 0);
    cudaStreamWaitEvent(s3, ev0, 0);

    // side streams: K/V splits, weight converts, zeroing
    split_kernel<<<gsx, blk, 0, s1>>>(k_in, xkh, xkl, n4x);
    cudaEventRecord(evSK, s1);
    split_kernel<<<gsx, blk, 0, s2>>>(v_in, xvh, xvl, n4x);
    cudaEventRecord(evSV, s2);
    wconv_kernel<<<gsw, blk, 0, s3>>>(Wq, wq16, n4w);
    wconv_kernel<<<gsw, blk, 0, s3>>>(Wk, wk16, n4w);
    wconv_kernel<<<gsw, blk, 0, s3>>>(Wv, wv16, n4w);
    wconv_kernel<<<gsw, blk, 0, s3>>>(Wo, wo16, n4w);
    zero_small<<<(NB * NH * DH * DH + 255) / 256, 256, 0, s3>>>();
    cudaEventRecord(evW, s3);

    // main stream
    split_kernel<<<gsx, blk>>>(q_in, xqh, xql, n4x);
    cudaStreamWaitEvent(0, evW, 0);
    gemm_mma<1><<<gg, blk, GSMEM>>>(xqh, xql, wq16, bq, pq);
    cudaStreamWaitEvent(0, evSK, 0);
    gemm_mma<1><<<gg, blk, GSMEM>>>(xkh, xkl, wk16, bk, pk);
    cudaStreamWaitEvent(0, evSV, 0);
    gemm_mma<0><<<gg, blk, GSMEM>>>(xvh, xvl, wv16, bv, pv);

    kv_kernel<<<dim3(8, NH, NB), blk>>>();
    attn_kernel<<<dim3(SL / 64, NH, NB), blk>>>();

    gemm_mma<0><<<gg, blk, GSMEM>>>(aoh, aol, wo16, bo, out);
}

// round 8
// speedup vs baseline: 3.2050x; 1.1247x over previous
#include <cuda_runtime.h>
#include <cuda_fp16.h>
#include <math.h>
#include <stdint.h>

#define NB 8
#define SL 8192
#define ED 512
#define NH 8
#define DH 64
#define MT (NB*SL)

// ---------------- scratch (device globals; no allocation) -------------------
__device__ float g_k[(size_t)MT * ED];    // K projection (feature-mapped), fp32
__device__ float g_v[(size_t)MT * ED];    // V projection, fp32
__device__ float g_kv[NB * NH * DH * DH];
__device__ float g_ksum[NB * NH * DH];
// input splits
__device__ __half g_xqh[(size_t)MT * ED];
__device__ __half g_xql[(size_t)MT * ED];
__device__ __half g_xkh[(size_t)MT * ED];
__device__ __half g_xkl[(size_t)MT * ED];
__device__ __half g_xvh[(size_t)MT * ED];
__device__ __half g_xvl[(size_t)MT * ED];
// Q projection (feature-mapped) fp16 hi/lo
__device__ __half g_qh[(size_t)MT * ED];
__device__ __half g_ql[(size_t)MT * ED];
// attn output splits
__device__ __half g_aoh[(size_t)MT * ED];
__device__ __half g_aol[(size_t)MT * ED];
// fp16 weights
__device__ __half g_w16[4][ED * ED];
// augmented KV blob (80 rows x 64 cols, swizzled): rows 0-63 KV, row 64 Ksum
__device__ __half g_kvah[NB * NH * 80 * 64];
__device__ __half g_kval[NB * NH * 80 * 64];

// ---------------- helpers ---------------------------------------------------
__device__ __forceinline__ uint32_t smem_u32(const void* p) {
    uint32_t a;
    asm("{ .reg .u64 t; cvta.to.shared.u64 t, %1; cvt.u32.u64 %0, t; }" : "=r"(a) : "l"(p));
    return a;
}
__device__ __forceinline__ uint32_t pack2h(__half a, __half b) {
    __half2 t(a, b);
    return *reinterpret_cast<uint32_t*>(&t);
}
__device__ __forceinline__ void cp16(uint32_t s, const void* g) {
    asm volatile("cp.async.cg.shared.global [%0], [%1], 16;" :: "r"(s), "l"(g));
}
#define CP_COMMIT() asm volatile("cp.async.commit_group;" ::: "memory")
#define CP_WAIT(N)  asm volatile("cp.async.wait_group %0;" :: "n"(N) : "memory")

#define LDSM4(r, addr)                                                         \
    asm volatile("ldmatrix.sync.aligned.m8n8.x4.shared.b16 {%0,%1,%2,%3}, [%4];" \
        : "=r"((r)[0]), "=r"((r)[1]), "=r"((r)[2]), "=r"((r)[3]) : "r"(addr))

#define MMA16816(d, a, b0, b1)                                                 \
    asm volatile("mma.sync.aligned.m16n8k16.row.col.f32.f16.f16.f32 "          \
        "{%0,%1,%2,%3}, {%4,%5,%6,%7}, {%8,%9}, {%0,%1,%2,%3};"                \
        : "+f"((d)[0]), "+f"((d)[1]), "+f"((d)[2]), "+f"((d)[3])               \
        : "r"((a)[0]), "r"((a)[1]), "r"((a)[2]), "r"((a)[3]), "r"(b0), "r"(b1))

// ---------------- split fp32 -> fp16 hi/lo -----------------------------------
__global__ __launch_bounds__(256) void split_kernel(const float* __restrict__ src,
                                                    __half* __restrict__ hi,
                                                    __half* __restrict__ lo, int n4)
{
    int i = blockIdx.x * blockDim.x + threadIdx.x;
    if (i >= n4) return;
    float4 v = ((const float4*)src)[i];
    __half h0 = __float2half_rn(v.x), h1 = __float2half_rn(v.y);
    __half h2 = __float2half_rn(v.z), h3 = __float2half_rn(v.w);
    __half l0 = __float2half_rn(v.x - __half2float(h0));
    __half l1 = __float2half_rn(v.y - __half2float(h1));
    __half l2 = __float2half_rn(v.z - __half2float(h2));
    __half l3 = __float2half_rn(v.w - __half2float(h3));
    uint2 hp, lp;
    hp.x = pack2h(h0, h1); hp.y = pack2h(h2, h3);
    lp.x = pack2h(l0, l1); lp.y = pack2h(l2, l3);
    ((uint2*)hi)[i] = hp;
    ((uint2*)lo)[i] = lp;
}

__global__ __launch_bounds__(256) void wconv_kernel(const float* __restrict__ src,
                                                    __half* __restrict__ dst, int n4)
{
    int i = blockIdx.x * blockDim.x + threadIdx.x;
    if (i >= n4) return;
    float4 v = ((const float4*)src)[i];
    uint2 p;
    p.x = pack2h(__float2half_rn(v.x), __float2half_rn(v.y));
    p.y = pack2h(__float2half_rn(v.z), __float2half_rn(v.w));
    ((uint2*)dst)[i] = p;
}

// ---------------- fp16 2-term GEMM (proven R5 config) ------------------------
#define AH_OFF   0
#define AL_OFF   16384
#define B_OFF    32768
#define STAGE_SZ 65536
#define GSMEM    (2 * STAGE_SZ)

__device__ __forceinline__ void issue_loads(uint32_t st,
                                            const __half* __restrict__ Ah,
                                            const __half* __restrict__ Al,
                                            const __half* __restrict__ Bh,
                                            int bm, int bn, int ch, int tid)
{
    const int kc = ch * 64;
#pragma unroll
    for (int i = 0; i < 2; i++) {
        const int idx = tid + i * 512;
        const int row = idx >> 3;
        const int c = idx & 7;
        const uint32_t soff = row * 128 + ((c ^ (row & 7)) << 4);
        const size_t goff = (size_t)(bm + row) * ED + kc + c * 8;
        cp16(st + AH_OFF + soff, Ah + goff);
        cp16(st + AL_OFF + soff, Al + goff);
    }
#pragma unroll
    for (int i = 0; i < 4; i++) {
        const int idx = tid + i * 512;
        const int row = idx >> 3;
        const int c = idx & 7;
        cp16(st + B_OFF + row * 128 + ((c ^ (row & 7)) << 4),
             Bh + (size_t)(bn + row) * ED + kc + c * 8);
    }
    CP_COMMIT();
}

template <int FEAT, int OUT16>
__global__ __launch_bounds__(512, 1) void gemm_mma(const __half* __restrict__ Ah,
                                                   const __half* __restrict__ Al,
                                                   const __half* __restrict__ Bh,
                                                   const float* __restrict__ bias,
                                                   float* __restrict__ C,
                                                   __half* __restrict__ Ch,
                                                   __half* __restrict__ Cl)
{
    extern __shared__ char smem_raw[];
    const uint32_t sb = smem_u32(smem_raw);

    const int tid = threadIdx.x;
    const int lane = tid & 31;
    const int wid = tid >> 5;
    const int wm = wid >> 2;
    const int wn = wid & 3;
    const int bm = blockIdx.y * 128;
    const int bn = blockIdx.x * 256;

    float acc[2][8][4];
#pragma unroll
    for (int i = 0; i < 2; i++)
#pragma unroll
        for (int j = 0; j < 8; j++)
#pragma unroll
            for (int q = 0; q < 4; q++) acc[i][j][q] = 0.f;

    issue_loads(sb, Ah, Al, Bh, bm, bn, 0, tid);

#pragma unroll 1
    for (int ch = 0; ch < 8; ch++) {
        const uint32_t cur = sb + (ch & 1) * STAGE_SZ;

        if (ch < 7) {
            issue_loads(sb + ((ch + 1) & 1) * STAGE_SZ, Ah, Al, Bh, bm, bn, ch + 1, tid);
            CP_WAIT(1);
        } else {
            CP_WAIT(0);
        }
        __syncthreads();

        const uint32_t sAh = cur + AH_OFF;
        const uint32_t sAl = cur + AL_OFF;
        const uint32_t sB  = cur + B_OFF;

        uint32_t fa[2][2][2][4];
        uint32_t fb[2][4];

        #define LOAD_A(s16, buf)                                               \
        {                                                                      \
            _Pragma("unroll")                                                  \
            for (int mf = 0; mf < 2; mf++) {                                   \
                const int arow = wm * 32 + mf * 16 + (lane & 15);              \
                const int achk = (s16) * 2 + (lane >> 4);                      \
                const uint32_t aoff = arow * 128 + ((achk ^ (arow & 7)) << 4); \
                LDSM4(fa[buf][mf][0], sAh + aoff);                             \
                LDSM4(fa[buf][mf][1], sAl + aoff);                             \
            }                                                                  \
        }
        #define LOAD_B(s16, nf, buf)                                           \
        {                                                                       \
            const int brow = wn * 64 + (nf) * 16 + (lane & 7) + ((lane >> 4) << 3); \
            const int bchk = (s16) * 2 + ((lane >> 3) & 1);                    \
            LDSM4(fb[buf], sB + brow * 128 + ((bchk ^ (brow & 7)) << 4));      \
        }

        LOAD_A(0, 0);
        LOAD_B(0, 0, 0);

#pragma unroll
        for (int s16 = 0; s16 < 4; s16++) {
            const int ab = s16 & 1;
#pragma unroll
            for (int nf = 0; nf < 4; nf++) {
                const int bb = nf & 1;
                if (nf < 3) {
                    LOAD_B(s16, nf + 1, bb ^ 1);
                } else if (s16 < 3) {
                    LOAD_A(s16 + 1, ab ^ 1);
                    LOAD_B(s16 + 1, 0, bb ^ 1);
                }
#pragma unroll
                for (int mf = 0; mf < 2; mf++) {
                    MMA16816(acc[mf][2 * nf],     fa[ab][mf][0], fb[bb][0], fb[bb][1]);
                    MMA16816(acc[mf][2 * nf + 1], fa[ab][mf][0], fb[bb][2], fb[bb][3]);
                }
#pragma unroll
                for (int mf = 0; mf < 2; mf++) {
                    MMA16816(acc[mf][2 * nf],     fa[ab][mf][1], fb[bb][0], fb[bb][1]);
                    MMA16816(acc[mf][2 * nf + 1], fa[ab][mf][1], fb[bb][2], fb[bb][3]);
                }
            }
        }
        #undef LOAD_A
        #undef LOAD_B
        __syncthreads();
    }

    // Epilogue
#pragma unroll
    for (int mf = 0; mf < 2; mf++) {
        const int row0 = bm + wm * 32 + mf * 16 + (lane >> 2);
#pragma unroll
        for (int nf8 = 0; nf8 < 8; nf8++) {
            const int col = bn + wn * 64 + nf8 * 8 + (lane & 3) * 2;
            const float b0 = bias[col], b1 = bias[col + 1];
            float x0 = acc[mf][nf8][0] + b0;
            float x1 = acc[mf][nf8][1] + b1;
            float x2 = acc[mf][nf8][2] + b0;
            float x3 = acc[mf][nf8][3] + b1;
            if (FEAT) {
                x0 = (x0 > 0.f) ? (x0 + 1.f) : expf(x0);
                x1 = (x1 > 0.f) ? (x1 + 1.f) : expf(x1);
                x2 = (x2 > 0.f) ? (x2 + 1.f) : expf(x2);
                x3 = (x3 > 0.f) ? (x3 + 1.f) : expf(x3);
            }
            if (OUT16) {
                __half h0 = __float2half_rn(x0), h1 = __float2half_rn(x1);
                __half h2 = __float2half_rn(x2), h3 = __float2half_rn(x3);
                __half e0 = __float2half_rn(x0 - __half2float(h0));
                __half e1 = __float2half_rn(x1 - __half2float(h1));
                __half e2 = __float2half_rn(x2 - __half2float(h2));
                __half e3 = __float2half_rn(x3 - __half2float(h3));
                *(uint32_t*)&Ch[(size_t)row0 * ED + col]       = pack2h(h0, h1);
                *(uint32_t*)&Cl[(size_t)row0 * ED + col]       = pack2h(e0, e1);
                *(uint32_t*)&Ch[(size_t)(row0 + 8) * ED + col] = pack2h(h2, h3);
                *(uint32_t*)&Cl[(size_t)(row0 + 8) * ED + col] = pack2h(e2, e3);
            } else {
                *(float2*)&C[(size_t)row0 * ED + col]       = make_float2(x0, x1);
                *(float2*)&C[(size_t)(row0 + 8) * ED + col] = make_float2(x2, x3);
            }
        }
    }
}

// ---------------- zeroing ----------------------------------------------------
__global__ void zero_small()
{
    int i = blockIdx.x * blockDim.x + threadIdx.x;
    if (i < NB * NH * DH * DH) g_kv[i] = 0.f;
    if (i < NB * NH * DH)      g_ksum[i] = 0.f;
}

// ---------------- KV (proven fp32 version, R1-R6) -----------------------------
__global__ __launch_bounds__(256) void kv_kernel()
{
    __shared__ float Ksh[32][64];
    __shared__ float Vsh[32][64];

    const int tid = threadIdx.x;
    const int sp = blockIdx.x;
    const int h = blockIdx.y;
    const int n = blockIdx.z;
    const int tx = tid & 15;
    const int ty = tid >> 4;
    const int s0 = sp * (SL / 8);

    float acc[4][4];
#pragma unroll
    for (int i = 0; i < 4; i++)
#pragma unroll
        for (int j = 0; j < 4; j++) acc[i][j] = 0.f;
    float ks = 0.f;

    for (int st = 0; st < SL / 8; st += 32) {
        __syncthreads();
#pragma unroll
        for (int t = tid; t < 512; t += 256) {
            const int r = t >> 4;
            const int c = (t & 15) * 4;
            const size_t g = ((size_t)(n * SL + s0 + st + r)) * ED + h * DH + c;
            *(float4*)&Ksh[r][c] = *(const float4*)&g_k[g];
            *(float4*)&Vsh[r][c] = *(const float4*)&g_v[g];
        }
        __syncthreads();
#pragma unroll 8
        for (int ss = 0; ss < 32; ss++) {
            float4 vm = *(const float4*)&Vsh[ss][ty * 4];
            float4 kd = *(const float4*)&Ksh[ss][tx * 4];
            const float a[4] = {vm.x, vm.y, vm.z, vm.w};
            const float b[4] = {kd.x, kd.y, kd.z, kd.w};
#pragma unroll
            for (int i = 0; i < 4; i++)
#pragma unroll
                for (int j = 0; j < 4; j++)
                    acc[i][j] = fmaf(a[i], b[j], acc[i][j]);
        }
        if (tid < 64) {
#pragma unroll 8
            for (int ss = 0; ss < 32; ss++) ks += Ksh[ss][tid];
        }
    }

    const int bse = (n * NH + h) * DH * DH;
#pragma unroll
    for (int i = 0; i < 4; i++)
#pragma unroll
        for (int j = 0; j < 4; j++)
            atomicAdd(&g_kv[bse + (ty * 4 + i) * DH + tx * 4 + j], acc[i][j]);
    if (tid < 64)
        atomicAdd(&g_ksum[(n * NH + h) * DH + tid], ks);
}

// ---------------- KV finalize: fp32 -> augmented fp16 hi/lo (swizzled) -------
__global__ __launch_bounds__(256) void kv_finalize()
{
    const int nh = blockIdx.x;
    const float* kv = g_kv + nh * 4096;
    const float* ks = g_ksum + nh * 64;
    char* oh = (char*)g_kvah + (size_t)nh * 10240;
    char* ol = (char*)g_kval + (size_t)nh * 10240;
    for (int idx = threadIdx.x; idx < 80 * 64; idx += 256) {
        const int r = idx >> 6, d = idx & 63;
        float x = (r < 64) ? kv[r * 64 + d] : (r == 64 ? ks[d] : 0.f);
        __half hh = __float2half_rn(x);
        __half ll = __float2half_rn(x - __half2float(hh));
        uint32_t off = r * 128 + d * 2;
        uint32_t sw = off ^ ((off >> 3) & 0x70);
        *(__half*)(oh + sw) = hh;
        *(__half*)(ol + sw) = ll;
    }
}

// ---------------- tensorized attn: out[l,m] = (Q KVaug^T)[l,m] / z[l] --------
#define AT_QH 0
#define AT_QL 16384
#define AT_BH 32768
#define AT_BL 43008
#define AT_SMEM 53248

__global__ __launch_bounds__(256) void attn_kernel()
{
    extern __shared__ char smem_raw[];
    const uint32_t sb = smem_u32(smem_raw);
    const int tid = threadIdx.x;
    const int lane = tid & 31;
    const int wid = tid >> 5;
    const int l0 = blockIdx.x * 128;
    const int h = blockIdx.y;
    const int n = blockIdx.z;
    const int nh = n * NH + h;

    // Q hi/lo tiles 128x64
#pragma unroll
    for (int it = 0; it < 8; it++) {
        int idx = tid + it * 256;
        int buf = idx >> 10;
        int r = (idx >> 3) & 127;
        int c = idx & 7;
        uint32_t soff = (buf ? AT_QL : AT_QH) + r * 128 + ((c ^ (r & 7)) << 4);
        const __half* src = buf ? g_ql : g_qh;
        cp16(sb + soff, src + (size_t)(n * SL + l0 + r) * ED + h * DH + c * 8);
    }
    // augmented KV blob (pre-swizzled, linear copy)
#pragma unroll
    for (int it = 0; it < 5; it++) {
        int idx = tid + it * 256;
        int buf = idx >= 640;
        int ch = buf ? idx - 640 : idx;
        cp16(sb + (buf ? AT_BL : AT_BH) + ch * 16,
             (buf ? g_kval : g_kvah) + (size_t)nh * 5120 + ch * 8);
    }
    CP_COMMIT();
    CP_WAIT(0);
    __syncthreads();

    float acc[9][4];
#pragma unroll
    for (int j = 0; j < 9; j++)
#pragma unroll
        for (int q = 0; q < 4; q++) acc[j][q] = 0.f;

#pragma unroll
    for (int kstep = 0; kstep < 4; kstep++) {
        uint32_t fah[4], fal[4];
        {
            const int arow = wid * 16 + (lane & 15);
            const int achk = kstep * 2 + (lane >> 4);
            const uint32_t aoff = arow * 128 + ((achk ^ (arow & 7)) << 4);
            LDSM4(fah, sb + AT_QH + aoff);
            LDSM4(fal, sb + AT_QL + aoff);
        }
        uint32_t fbh[5][4], fbl[5][4];
#pragma unroll
        for (int p = 0; p < 5; p++) {
            const int brow = p * 16 + (lane & 7) + ((lane >> 4) << 3);
            const int bchk = kstep * 2 + ((lane >> 3) & 1);
            const uint32_t boff = brow * 128 + ((bchk ^ (brow & 7)) << 4);
            LDSM4(fbh[p], sb + AT_BH + boff);
            LDSM4(fbl[p], sb + AT_BL + boff);
        }
#pragma unroll
        for (int j = 0; j < 9; j++) {
            uint32_t bh0 = fbh[j >> 1][(j & 1) * 2], bh1 = fbh[j >> 1][(j & 1) * 2 + 1];
            uint32_t bl0 = fbl[j >> 1][(j & 1) * 2], bl1 = fbl[j >> 1][(j & 1) * 2 + 1];
            MMA16816(acc[j], fah, bh0, bh1);
            MMA16816(acc[j], fah, bl0, bl1);
            MMA16816(acc[j], fal, bh0, bh1);
        }
    }

    const float zd0 = __shfl_sync(0xFFFFFFFFu, acc[8][0], lane & ~3);
    const float zd1 = __shfl_sync(0xFFFFFFFFu, acc[8][2], lane & ~3);
    const float z0 = 1.f / (fmaxf(zd0, 0.f) + 1e-6f);
    const float z1 = 1.f / (fmaxf(zd1, 0.f) + 1e-6f);
    const int g = lane >> 2, tig = lane & 3;
    const int row0 = l0 + wid * 16 + g;

#pragma unroll
    for (int j = 0; j < 8; j++) {
        const int e = h * DH + j * 8 + tig * 2;
        float x0 = acc[j][0] * z0, x1 = acc[j][1] * z0;
        float x2 = acc[j][2] * z1, x3 = acc[j][3] * z1;
        __half h0 = __float2half_rn(x0), h1 = __float2half_rn(x1);
        __half h2 = __float2half_rn(x2), h3 = __float2half_rn(x3);
        __half e0 = __float2half_rn(x0 - __half2float(h0));
        __half e1 = __float2half_rn(x1 - __half2float(h1));
        __half e2 = __float2half_rn(x2 - __half2float(h2));
        __half e3 = __float2half_rn(x3 - __half2float(h3));
        *(uint32_t*)&g_aoh[(size_t)(n * SL + row0) * ED + e]     = pack2h(h0, h1);
        *(uint32_t*)&g_aol[(size_t)(n * SL + row0) * ED + e]     = pack2h(e0, e1);
        *(uint32_t*)&g_aoh[(size_t)(n * SL + row0 + 8) * ED + e] = pack2h(h2, h3);
        *(uint32_t*)&g_aol[(size_t)(n * SL + row0 + 8) * ED + e] = pack2h(e2, e3);
    }
}

// ---------------- launch -----------------------------------------------------
extern "C" void kernel_launch(void* const* d_in, const int* in_sizes, int n_in,
                              void* d_out, int out_size)
{
    const float* q_in = (const float*)d_in[0];
    const float* k_in = (const float*)d_in[1];
    const float* v_in = (const float*)d_in[2];
    const float* Wq = (const float*)d_in[3];
    const float* bq = (const float*)d_in[4];
    const float* Wk = (const float*)d_in[5];
    const float* bk = (const float*)d_in[6];
    const float* Wv = (const float*)d_in[7];
    const float* bv = (const float*)d_in[8];
    const float* Wo = (const float*)d_in[9];
    const float* bo = (const float*)d_in[10];
    float* out = (float*)d_out;

    float *pk, *pv;
    __half *xqh, *xql, *xkh, *xkl, *xvh, *xvl, *qh, *ql, *aoh, *aol, *w16;
    cudaGetSymbolAddress((void**)&pk, g_k);
    cudaGetSymbolAddress((void**)&pv, g_v);
    cudaGetSymbolAddress((void**)&xqh, g_xqh);
    cudaGetSymbolAddress((void**)&xql, g_xql);
    cudaGetSymbolAddress((void**)&xkh, g_xkh);
    cudaGetSymbolAddress((void**)&xkl, g_xkl);
    cudaGetSymbolAddress((void**)&xvh, g_xvh);
    cudaGetSymbolAddress((void**)&xvl, g_xvl);
    cudaGetSymbolAddress((void**)&qh, g_qh);
    cudaGetSymbolAddress((void**)&ql, g_ql);
    cudaGetSymbolAddress((void**)&aoh, g_aoh);
    cudaGetSymbolAddress((void**)&aol, g_aol);
    cudaGetSymbolAddress((void**)&w16, g_w16);
    __half* wq16 = w16;
    __half* wk16 = w16 + (size_t)ED * ED;
    __half* wv16 = w16 + (size_t)2 * ED * ED;
    __half* wo16 = w16 + (size_t)3 * ED * ED;

    static cudaStream_t s1, s2, s3;
    static cudaEvent_t ev0, evSK, evSV, evSQ, evW, evGV, evGQ;
    static bool inited = false;
    if (!inited) {
        cudaStreamCreateWithFlags(&s1, cudaStreamNonBlocking);
        cudaStreamCreateWithFlags(&s2, cudaStreamNonBlocking);
        cudaStreamCreateWithFlags(&s3, cudaStreamNonBlocking);
        cudaEventCreateWithFlags(&ev0, cudaEventDisableTiming);
        cudaEventCreateWithFlags(&evSK, cudaEventDisableTiming);
        cudaEventCreateWithFlags(&evSV, cudaEventDisableTiming);
        cudaEventCreateWithFlags(&evSQ, cudaEventDisableTiming);
        cudaEventCreateWithFlags(&evW, cudaEventDisableTiming);
        cudaEventCreateWithFlags(&evGV, cudaEventDisableTiming);
        cudaEventCreateWithFlags(&evGQ, cudaEventDisableTiming);
        cudaFuncSetAttribute(gemm_mma<1,0>, cudaFuncAttributeMaxDynamicSharedMemorySize, GSMEM);
        cudaFuncSetAttribute(gemm_mma<1,1>, cudaFuncAttributeMaxDynamicSharedMemorySize, GSMEM);
        cudaFuncSetAttribute(gemm_mma<0,0>, cudaFuncAttributeMaxDynamicSharedMemorySize, GSMEM);
        cudaFuncSetAttribute(attn_kernel, cudaFuncAttributeMaxDynamicSharedMemorySize, AT_SMEM);
        inited = true;
    }

    const int n4x = (int)((size_t)MT * ED / 4);
    const int n4w = ED * ED / 4;
    dim3 blk(256);
    dim3 gblk(512);
    dim3 gsx((n4x + 255) / 256);
    dim3 gsw((n4w + 255) / 256);
    dim3 gg(ED / 256, MT / 128);

    // fork
    cudaEventRecord(ev0, 0);
    cudaStreamWaitEvent(s1, ev0, 0);
    cudaStreamWaitEvent(s2, ev0, 0);
    cudaStreamWaitEvent(s3, ev0, 0);

    // s3: weight converts + zero
    wconv_kernel<<<gsw, blk, 0, s3>>>(Wq, wq16, n4w);
    wconv_kernel<<<gsw, blk, 0, s3>>>(Wk, wk16, n4w);
    wconv_kernel<<<gsw, blk, 0, s3>>>(Wv, wv16, n4w);
    wconv_kernel<<<gsw, blk, 0, s3>>>(Wo, wo16, n4w);
    zero_small<<<(NB * NH * DH * DH + 255) / 256, 256, 0, s3>>>();
    cudaEventRecord(evW, s3);

    // s1: split K
    split_kernel<<<gsx, blk, 0, s1>>>(k_in, xkh, xkl, n4x);
    cudaEventRecord(evSK, s1);
    // s2: split V
    split_kernel<<<gsx, blk, 0, s2>>>(v_in, xvh, xvl, n4x);
    cudaEventRecord(evSV, s2);

    // main: split Q
    split_kernel<<<gsx, blk>>>(q_in, xqh, xql, n4x);
    cudaEventRecord(evSQ, 0);

    // main: gemmK (fp32 out), gemmV (fp32 out)
    cudaStreamWaitEvent(0, evW, 0);
    cudaStreamWaitEvent(0, evSK, 0);
    gemm_mma<1,0><<<gg, gblk, GSMEM>>>(xkh, xkl, wk16, bk, pk, nullptr, nullptr);
    cudaStreamWaitEvent(0, evSV, 0);
    gemm_mma<0,0><<<gg, gblk, GSMEM>>>(xvh, xvl, wv16, bv, pv, nullptr, nullptr);
    cudaEventRecord(evGV, 0);

    // s1: gemmQ (fp16 out) overlapping kv on main
    cudaStreamWaitEvent(s1, evSQ, 0);
    cudaStreamWaitEvent(s1, evW, 0);
    cudaStreamWaitEvent(s1, evGV, 0);
    gemm_mma<1,1><<<gg, gblk, GSMEM, s1>>>(xqh, xql, wq16, bq, nullptr, qh, ql);
    cudaEventRecord(evGQ, s1);

    // main: kv (fp32, proven) + finalize
    kv_kernel<<<dim3(8, NH, NB), blk>>>();
    kv_finalize<<<NB * NH, blk>>>();

    // main: attn (needs gemmQ)
    cudaStreamWaitEvent(0, evGQ, 0);
    attn_kernel<<<dim3(SL / 128, NH, NB), blk, AT_SMEM>>>();

    // main: output GEMM
    gemm_mma<0,0><<<gg, gblk, GSMEM>>>(aoh, aol, wo16, bo, out, nullptr, nullptr);
}